// round 11
// baseline (speedup 1.0000x reference)
#include <cuda_runtime.h>
#include <cuda_bf16.h>
#include <stdint.h>

// ---------------------------------------------------------------------------
// Problem constants
// ---------------------------------------------------------------------------
#define Bb 8
#define Ss 32
#define Nn 1024
#define Hh 128
#define NBROWS 8192
#define NBH 1048576
#define NHf 131072
#define G3 384

// ---------------------------------------------------------------------------
// Scratch (device globals; no allocation allowed). Node-major rows r = n*8+b.
// ---------------------------------------------------------------------------
__device__ __align__(16) __nv_bfloat16 g_adjH[1024 * 1024], g_adjL[1024 * 1024];
__device__ __align__(16) __nv_bfloat16 g_xTH[1024 * 1024], g_xTL[1024 * 1024];
__device__ __align__(16) __nv_bfloat16 g_hidTH[1024 * 1024], g_hidTL[1024 * 1024];
__device__ __align__(16) __nv_bfloat16 g_wcH[512 * 128], g_wcL[512 * 128];
__device__ __align__(16) __nv_bfloat16 g_wihH[512 * 128], g_wihL[512 * 128];
__device__ __align__(16) __nv_bfloat16 g_whhH[512 * 128], g_whhL[512 * 128];
__device__ __align__(16) __nv_bfloat16 g_csH[8192 * 128], g_csL[8192 * 128];

__device__ float g_W4[4 * 512];          // Wc rows 0..3, layout [k][gate]
__device__ float g_AX[1024 * 1024];
__device__ float g_G[NBROWS * 512];
__device__ float g_Gc[NBROWS * 512];
__device__ volatile unsigned int g_bar;  // grid barrier counter (zeroed per launch)

// ---------------------------------------------------------------------------
// Helpers
// ---------------------------------------------------------------------------
__device__ __forceinline__ float fsigm(float x) {
    return __fdividef(1.f, 1.f + __expf(-x));
}
__device__ __forceinline__ float ftanh(float x) {
    return 1.f - __fdividef(2.f, __expf(2.f * x) + 1.f);
}

__device__ __forceinline__ uint32_t smem_u32(const void* p) {
    uint32_t a;
    asm("{ .reg .u64 t; cvta.to.shared.u64 t, %1; cvt.u32.u64 %0, t; }" : "=r"(a) : "l"(p));
    return a;
}

__device__ __forceinline__ void splitHL(float v, __nv_bfloat16& h, __nv_bfloat16& l) {
    h = __float2bfloat16(v);
    l = __float2bfloat16(v - __bfloat162float(h));
}
__device__ __forceinline__ uint32_t pack2(float v0, float v1) {
    __nv_bfloat16 a = __float2bfloat16(v0), b = __float2bfloat16(v1);
    return (uint32_t)*(unsigned short*)&a | ((uint32_t)*(unsigned short*)&b << 16);
}
__device__ __forceinline__ uint32_t pack2lo(float v0, float v1) {
    __nv_bfloat16 a = __float2bfloat16(v0);
    __nv_bfloat16 b = __float2bfloat16(v1);
    float l0 = v0 - __bfloat162float(a), l1 = v1 - __bfloat162float(b);
    __nv_bfloat16 c = __float2bfloat16(l0), d = __float2bfloat16(l1);
    return (uint32_t)*(unsigned short*)&c | ((uint32_t)*(unsigned short*)&d << 16);
}

#define MMA_BF16(c, a, b)                                                     \
    asm volatile(                                                             \
        "mma.sync.aligned.m16n8k16.row.col.f32.bf16.bf16.f32 "                \
        "{%0,%1,%2,%3},{%4,%5,%6,%7},{%8,%9},{%0,%1,%2,%3};"                  \
        : "+f"((c)[0]), "+f"((c)[1]), "+f"((c)[2]), "+f"((c)[3])              \
        : "r"((a)[0]), "r"((a)[1]), "r"((a)[2]), "r"((a)[3]),                 \
          "r"((b)[0]), "r"((b)[1]))

#define LDSM4(r0, r1, r2, r3, addr)                                           \
    asm volatile("ldmatrix.sync.aligned.m8n8.x4.shared.b16 {%0,%1,%2,%3},[%4];" \
                 : "=r"(r0), "=r"(r1), "=r"(r2), "=r"(r3) : "r"(addr))

#define CPASYNC16(s, g)                                                       \
    asm volatile("cp.async.cg.shared.global [%0], [%1], 16;" :: "r"(s), "l"(g))
#define CPCOMMIT() asm volatile("cp.async.commit_group;")
#define CPWAIT1()  asm volatile("cp.async.wait_group 1;")
#define CPWAIT0()  asm volatile("cp.async.wait_group 0;")

// Grid barrier: release fence + atomic arrive + bounded acquire spin.
// Safe: 128 CTAs, 1/SM occupancy on 148 SMs -> all co-resident.
__device__ __forceinline__ void gridbar(int ph) {
    __syncthreads();
    if (threadIdx.x == 0) {
        __threadfence();
        atomicAdd((unsigned int*)&g_bar, 1u);
        const unsigned int tgt = (unsigned int)ph * 128u;
        for (long i = 0; i < (1L << 33) && g_bar < tgt; i++) { }
        __threadfence();
    }
    __syncthreads();
}

// ---------------------------------------------------------------------------
// 3xBF16 split GEMM (standalone, fp32 C epilogue). C = A @ B^T.
// BM=64, BN template (64/128), BK=32, 256 threads. grid = (N/BN, M/64).
// ---------------------------------------------------------------------------
template <int BN>
__global__ void __launch_bounds__(256) gemmA(
    const __nv_bfloat16* __restrict__ Ah, const __nv_bfloat16* __restrict__ Al,
    const __nv_bfloat16* __restrict__ Bh, const __nv_bfloat16* __restrict__ Bl,
    float* __restrict__ C, int K, int N)
{
    constexpr int NI = BN / 32;
    constexpr int STG = 5120 + 2 * BN * 40;

    extern __shared__ __nv_bfloat16 smem[];
    const uint32_t sb0 = smem_u32(smem);

    const int tid = threadIdx.x;
    const int lane = tid & 31;
    const int wid = tid >> 5;
    const int wm = wid >> 2;
    const int wn = wid & 3;
    const int g = lane >> 2;
    const int ti = lane & 3;

    const int bm = blockIdx.y * 64;
    const int bn = blockIdx.x * BN;

    const int arow = tid >> 2;
    const int akq = tid & 3;

    const int i1 = (lane >> 3) & 1, i2 = lane >> 4, l7 = lane & 7;
    const uint32_t aoff = ((wm * 32 + i1 * 8 + l7) * 40 + i2 * 8) * 2;
    const uint32_t boff = (5120 + (wn * (BN / 4) + i2 * 8 + l7) * 40 + i1 * 8) * 2;

    float acc[2][NI][4];
#pragma unroll
    for (int i = 0; i < 2; i++)
#pragma unroll
        for (int j = 0; j < NI; j++)
#pragma unroll
            for (int v = 0; v < 4; v++) acc[i][j][v] = 0.f;

    const int nk = K >> 5;

    auto load_stage = [&](int stage, int k0) {
        const uint32_t sb = sb0 + stage * STG * 2;
        {
            const uint32_t so = sb + (arow * 40 + akq * 8) * 2;
            CPASYNC16(so, Ah + (size_t)(bm + arow) * K + k0 + akq * 8);
            CPASYNC16(so + 2560 * 2, Al + (size_t)(bm + arow) * K + k0 + akq * 8);
        }
#pragma unroll
        for (int rep = 0; rep < BN / 64; rep++) {
            const int idx = tid + rep * 256;
            const int brow = idx >> 2;
            const int bkq = idx & 3;
            const uint32_t so = sb + (5120 + brow * 40 + bkq * 8) * 2;
            CPASYNC16(so, Bh + (size_t)(bn + brow) * K + k0 + bkq * 8);
            CPASYNC16(so + BN * 40 * 2, Bl + (size_t)(bn + brow) * K + k0 + bkq * 8);
        }
        CPCOMMIT();
    };

    load_stage(0, 0);

    for (int kt = 0; kt < nk; kt++) {
        if (kt + 1 < nk) { load_stage((kt + 1) & 1, (kt + 1) * 32); CPWAIT1(); }
        else             { CPWAIT0(); }
        __syncthreads();

        const uint32_t sb = sb0 + (kt & 1) * STG * 2;
#pragma unroll
        for (int q = 0; q < 2; q++) {
            uint32_t ah[2][4], al[2][4], bh[NI][2], bl[NI][2];
            const uint32_t ka = sb + aoff + q * 32;
            LDSM4(ah[0][0], ah[0][1], ah[0][2], ah[0][3], ka);
            LDSM4(ah[1][0], ah[1][1], ah[1][2], ah[1][3], ka + 1280);
            LDSM4(al[0][0], al[0][1], al[0][2], al[0][3], ka + 5120);
            LDSM4(al[1][0], al[1][1], al[1][2], al[1][3], ka + 5120 + 1280);
            const uint32_t kb = sb + boff + q * 32;
#pragma unroll
            for (int p = 0; p < NI / 2; p++) {
                LDSM4(bh[2 * p][0], bh[2 * p][1], bh[2 * p + 1][0], bh[2 * p + 1][1],
                      kb + p * 1280);
                LDSM4(bl[2 * p][0], bl[2 * p][1], bl[2 * p + 1][0], bl[2 * p + 1][1],
                      kb + BN * 80 + p * 1280);
            }
#pragma unroll
            for (int mi = 0; mi < 2; mi++)
#pragma unroll
                for (int ni = 0; ni < NI; ni++) {
                    MMA_BF16(acc[mi][ni], ah[mi], bh[ni]);
                    MMA_BF16(acc[mi][ni], ah[mi], bl[ni]);
                    MMA_BF16(acc[mi][ni], al[mi], bh[ni]);
                }
        }
        __syncthreads();
    }

#pragma unroll
    for (int mi = 0; mi < 2; mi++) {
        const int row = bm + wm * 32 + mi * 16 + g;
#pragma unroll
        for (int ni = 0; ni < NI; ni++) {
            const int col = bn + wn * (BN / 4) + ni * 8 + 2 * ti;
            *(float2*)(C + (size_t)row * N + col) =
                make_float2(acc[mi][ni][0], acc[mi][ni][1]);
            *(float2*)(C + (size_t)(row + 8) * N + col) =
                make_float2(acc[mi][ni][2], acc[mi][ni][3]);
        }
    }
}

#define SMEM_B128 (2 * (5120 + 2 * 128 * 40) * 2)   // 61440
#define SMEM_B64  (2 * (5120 + 2 * 64 * 40) * 2)    // 40960

// ---------------------------------------------------------------------------
// PERSISTENT ENCODER MEGAKERNEL: all 32 steps in one launch.
// grid = (16 n-tiles, 8 batches) = 128 CTAs, 256 threads, 75776 B smem.
// Per step: [phase1 AC(64x128,K=1024) in smem] [phase2 G(64x512,K=128)]
//           gridbar -> elementwise (8x 32x32 tiles, csum in regs) -> gridbar.
// ---------------------------------------------------------------------------
#define STG1 15360
#define SMEM_STEP 75776

__global__ void __launch_bounds__(256) k_enc_all(
    const float* __restrict__ b1, const float* __restrict__ b2)
{
    extern __shared__ __nv_bfloat16 smem[];
    float* tf = (float*)smem;              // 32x33 staging (elementwise)
    const uint32_t sb0 = smem_u32(smem);

    const int tid = threadIdx.x;
    const int lane = tid & 31;
    const int wid = tid >> 5;
    const int wm = wid >> 2;
    const int wn = wid & 3;
    const int g = lane >> 2;
    const int ti = lane & 3;
    const int bm = blockIdx.x * 64;       // n-tile base
    const int b = blockIdx.y;             // batch

    const __nv_bfloat16* BH = g_hidTH + (size_t)b * 128 * 1024;
    const __nv_bfloat16* BL = g_hidTL + (size_t)b * 128 * 1024;

    const int arow = tid >> 2;
    const int akq = tid & 3;
    const int i1 = (lane >> 3) & 1, i2 = lane >> 4, l7 = lane & 7;
    const uint32_t aoff = ((wm * 32 + i1 * 8 + l7) * 40 + i2 * 8) * 2;
    const uint32_t boff = (5120 + (wn * 32 + i2 * 8 + l7) * 40 + i1 * 8) * 2;
    const uint32_t aoff2 = ((wm * 32 + i1 * 8 + l7) * 136 + i2 * 8) * 2;
    const uint32_t boff2 = ((wn * 32 + i2 * 8 + l7) * 40 + i1 * 8) * 2;

    // elementwise thread coords
    const int hl = tid & 31;
    const int w8 = tid >> 5;

    float cs[32];                          // csum registers: [tile][q]
#pragma unroll
    for (int i = 0; i < 32; i++) cs[i] = 0.f;

    int ph = 0;                            // barrier phase

    for (int s = 0; s < Ss; s++) {
        if (s) {
            // ================ phase 1: AC = adj_tile @ hidT_b^T ================
            float acc[2][4][4];
#pragma unroll
            for (int i = 0; i < 2; i++)
#pragma unroll
                for (int j = 0; j < 4; j++)
#pragma unroll
                    for (int v = 0; v < 4; v++) acc[i][j][v] = 0.f;

            auto load_stage = [&](int stage, int k0) {
                const uint32_t sb = sb0 + stage * STG1 * 2;
                {
                    const uint32_t so = sb + (arow * 40 + akq * 8) * 2;
                    CPASYNC16(so, g_adjH + (size_t)(bm + arow) * 1024 + k0 + akq * 8);
                    CPASYNC16(so + 2560 * 2, g_adjL + (size_t)(bm + arow) * 1024 + k0 + akq * 8);
                }
#pragma unroll
                for (int rep = 0; rep < 2; rep++) {
                    const int idx = tid + rep * 256;
                    const int brow = idx >> 2;
                    const int bkq = idx & 3;
                    const uint32_t so = sb + (5120 + brow * 40 + bkq * 8) * 2;
                    CPASYNC16(so, BH + (size_t)brow * 1024 + k0 + bkq * 8);
                    CPASYNC16(so + 10240, BL + (size_t)brow * 1024 + k0 + bkq * 8);
                }
                CPCOMMIT();
            };

            load_stage(0, 0);

            for (int kt = 0; kt < 32; kt++) {
                if (kt + 1 < 32) { load_stage((kt + 1) & 1, (kt + 1) * 32); CPWAIT1(); }
                else             { CPWAIT0(); }
                __syncthreads();

                const uint32_t sb = sb0 + (kt & 1) * STG1 * 2;
#pragma unroll
                for (int q = 0; q < 2; q++) {
                    uint32_t ah[2][4], al[2][4], bh[4][2], bl[4][2];
                    const uint32_t ka = sb + aoff + q * 32;
                    LDSM4(ah[0][0], ah[0][1], ah[0][2], ah[0][3], ka);
                    LDSM4(ah[1][0], ah[1][1], ah[1][2], ah[1][3], ka + 1280);
                    LDSM4(al[0][0], al[0][1], al[0][2], al[0][3], ka + 5120);
                    LDSM4(al[1][0], al[1][1], al[1][2], al[1][3], ka + 5120 + 1280);
                    const uint32_t kb = sb + boff + q * 32;
#pragma unroll
                    for (int p = 0; p < 2; p++) {
                        LDSM4(bh[2 * p][0], bh[2 * p][1], bh[2 * p + 1][0], bh[2 * p + 1][1],
                              kb + p * 1280);
                        LDSM4(bl[2 * p][0], bl[2 * p][1], bl[2 * p + 1][0], bl[2 * p + 1][1],
                              kb + 10240 + p * 1280);
                    }
#pragma unroll
                    for (int mi = 0; mi < 2; mi++)
#pragma unroll
                        for (int ni = 0; ni < 4; ni++) {
                            MMA_BF16(acc[mi][ni], ah[mi], bh[ni]);
                            MMA_BF16(acc[mi][ni], ah[mi], bl[ni]);
                            MMA_BF16(acc[mi][ni], al[mi], bh[ni]);
                        }
                }
                __syncthreads();
            }

            // AC -> SMEM (split hi/lo), rows stride 136
#pragma unroll
            for (int mi = 0; mi < 2; mi++) {
                const int row = wm * 32 + mi * 16 + g;
#pragma unroll
                for (int ni = 0; ni < 4; ni++) {
                    const int col = wn * 32 + ni * 8 + 2 * ti;
                    const uint32_t o0 = (uint32_t)(row * 136 + col) * 2;
                    const uint32_t o1 = (uint32_t)((row + 8) * 136 + col) * 2;
                    asm volatile("st.shared.b32 [%0], %1;" :: "r"(sb0 + o0),
                                 "r"(pack2(acc[mi][ni][0], acc[mi][ni][1])));
                    asm volatile("st.shared.b32 [%0], %1;" :: "r"(sb0 + 17408 + o0),
                                 "r"(pack2lo(acc[mi][ni][0], acc[mi][ni][1])));
                    asm volatile("st.shared.b32 [%0], %1;" :: "r"(sb0 + o1),
                                 "r"(pack2(acc[mi][ni][2], acc[mi][ni][3])));
                    asm volatile("st.shared.b32 [%0], %1;" :: "r"(sb0 + 17408 + o1),
                                 "r"(pack2lo(acc[mi][ni][2], acc[mi][ni][3])));
                }
            }
            __syncthreads();

            // ================ phase 2: G = AC @ Wc^T (K=128) ================
            auto loadWc = [&](int idx, int st) {
                const uint32_t base = sb0 + (17408 + st * 10240) * 2;
                const int nc2 = idx >> 2, kc2 = idx & 3;
#pragma unroll
                for (int rep = 0; rep < 2; rep++) {
                    const int e = tid + rep * 256;
                    const int row = e >> 2, q4 = e & 3;
                    const uint32_t dst = base + (row * 40 + q4 * 8) * 2;
                    CPASYNC16(dst, g_wcH + (nc2 * 128 + row) * 128 + kc2 * 32 + q4 * 8);
                    CPASYNC16(dst + 5120 * 2, g_wcL + (nc2 * 128 + row) * 128 + kc2 * 32 + q4 * 8);
                }
                CPCOMMIT();
            };

            loadWc(0, 0);

            for (int nc = 0; nc < 4; nc++) {
                float acc2[2][4][4];
#pragma unroll
                for (int i = 0; i < 2; i++)
#pragma unroll
                    for (int j = 0; j < 4; j++)
#pragma unroll
                        for (int v = 0; v < 4; v++) acc2[i][j][v] = 0.f;

                for (int kc = 0; kc < 4; kc++) {
                    const int gi = nc * 4 + kc;
                    if (gi < 15) { loadWc(gi + 1, (gi + 1) & 1); CPWAIT1(); }
                    else         { CPWAIT0(); }
                    __syncthreads();
                    const uint32_t wcb = sb0 + (17408 + (gi & 1) * 10240) * 2;
#pragma unroll
                    for (int q = 0; q < 2; q++) {
                        uint32_t ah[2][4], al[2][4], bh[4][2], bl[4][2];
                        const uint32_t ka = sb0 + aoff2 + (kc * 32 + q * 16) * 2;
                        LDSM4(ah[0][0], ah[0][1], ah[0][2], ah[0][3], ka);
                        LDSM4(ah[1][0], ah[1][1], ah[1][2], ah[1][3], ka + 4352);
                        LDSM4(al[0][0], al[0][1], al[0][2], al[0][3], ka + 17408);
                        LDSM4(al[1][0], al[1][1], al[1][2], al[1][3], ka + 17408 + 4352);
                        const uint32_t kb = wcb + boff2 + q * 32;
#pragma unroll
                        for (int p = 0; p < 2; p++) {
                            LDSM4(bh[2 * p][0], bh[2 * p][1], bh[2 * p + 1][0], bh[2 * p + 1][1],
                                  kb + p * 1280);
                            LDSM4(bl[2 * p][0], bl[2 * p][1], bl[2 * p + 1][0], bl[2 * p + 1][1],
                                  kb + 10240 + p * 1280);
                        }
#pragma unroll
                        for (int mi = 0; mi < 2; mi++)
#pragma unroll
                            for (int ni = 0; ni < 4; ni++) {
                                MMA_BF16(acc2[mi][ni], ah[mi], bh[ni]);
                                MMA_BF16(acc2[mi][ni], ah[mi], bl[ni]);
                                MMA_BF16(acc2[mi][ni], al[mi], bh[ni]);
                            }
                    }
                    __syncthreads();
                }

#pragma unroll
                for (int mi = 0; mi < 2; mi++) {
                    const int n0 = bm + wm * 32 + mi * 16 + g;
#pragma unroll
                    for (int ni = 0; ni < 4; ni++) {
                        const int col = nc * 128 + wn * 32 + ni * 8 + 2 * ti;
                        *(float2*)(g_G + ((size_t)n0 * 8 + b) * 512 + col) =
                            make_float2(acc2[mi][ni][0], acc2[mi][ni][1]);
                        *(float2*)(g_G + ((size_t)(n0 + 8) * 8 + b) * 512 + col) =
                            make_float2(acc2[mi][ni][2], acc2[mi][ni][3]);
                    }
                }
            }
            gridbar(++ph);   // G visible to all CTAs
        }

        // ================ phase 3: elementwise (8 tiles of 32x32) ================
        const int sb4 = s * 32 + b * 4;
#pragma unroll
        for (int tile = 0; tile < 8; tile++) {
            const int n0 = bm + (tile >> 2) * 32;
            const int h0 = (tile & 3) * 32;
#pragma unroll
            for (int q = 0; q < 4; q++) {
                const int n = n0 + w8 + q * 8;
                const int h = h0 + hl;
                const int j = n * 128 + h;
                const int ji = j + NHf;
                const int ni = ji / G3, ci = ji - ni * G3;
                const int jo = j + 2 * NHf;
                const int no = jo / G3, co = jo - no * G3;

                float igp = g_G[(size_t)(ni * 8 + b) * 512 + ci] + b1[ci];
                float ogp = g_G[(size_t)(no * 8 + b) * 512 + co] + b1[co];
                float csp = g_G[(size_t)(n * 8 + b) * 512 + G3 + h] + b2[h];
#pragma unroll
                for (int k = 0; k < 4; k++) {
                    igp += g_AX[(size_t)ni * 1024 + sb4 + k] * g_W4[k * 512 + ci];
                    ogp += g_AX[(size_t)no * 1024 + sb4 + k] * g_W4[k * 512 + co];
                    csp += g_AX[(size_t)n * 1024 + sb4 + k] * g_W4[k * 512 + G3 + h];
                }
                const float hn = fsigm(ogp) * ftanh(fsigm(igp) * ftanh(csp));
                cs[tile * 4 + q] += hn;
                tf[hl * 33 + (w8 + q * 8)] = hn;
            }
            __syncthreads();
#pragma unroll
            for (int q = 0; q < 4; q++) {
                const int h2 = w8 + q * 8;
                const float v = tf[h2 * 33 + hl];
                __nv_bfloat16 hh, ll;
                splitHL(v, hh, ll);
                g_hidTH[(size_t)(b * 128 + h0 + h2) * 1024 + n0 + hl] = hh;
                g_hidTL[(size_t)(b * 128 + h0 + h2) * 1024 + n0 + hl] = ll;
            }
            __syncthreads();
        }
        if (s < Ss - 1) gridbar(++ph);   // hidT visible before next phase1
    }

    // write split csum from registers
#pragma unroll
    for (int tile = 0; tile < 8; tile++) {
        const int n0 = bm + (tile >> 2) * 32;
        const int h0 = (tile & 3) * 32;
#pragma unroll
        for (int q = 0; q < 4; q++) {
            const int n = n0 + w8 + q * 8;
            const int h = h0 + hl;
            const size_t o = (size_t)(n * 8 + b) * 128 + h;
            __nv_bfloat16 ch, cl;
            splitHL(cs[tile * 4 + q], ch, cl);
            g_csH[o] = ch;
            g_csL[o] = cl;
        }
    }
}

// ---------------------------------------------------------------------------
// Persistent fused decoder: 32 LSTM steps in ONE launch (proven).
// grid 128 CTAs x 512 threads. Writes the (b,n,h)-permuted output directly.
// ---------------------------------------------------------------------------
#define DEC_AH 0
#define DEC_AL 8704
#define DEC_B0 17408
#define DEC_STG 40960
#define DEC_ELEMS (DEC_B0 + 2 * DEC_STG)
#define DEC_SMEM (DEC_ELEMS * 2)

__global__ void __launch_bounds__(512) k_dec(const float* __restrict__ Gc,
                                             const float* __restrict__ bih,
                                             const float* __restrict__ bhh,
                                             float* __restrict__ out)
{
    extern __shared__ __nv_bfloat16 sm[];
    __shared__ float sbias[512];
    const uint32_t sb = smem_u32(sm);

    const int tid = threadIdx.x;
    const int lane = tid & 31;
    const int wid = tid >> 5;
    const int wm = wid >> 3;
    const int wn = wid & 7;
    const int g = lane >> 2;
    const int ti = lane & 3;
    const int bm = blockIdx.x * 64;

    if (tid < 512) sbias[tid] = bih[tid] + bhh[tid];
    for (int i = tid; i < 8704; i += 512) { sm[DEC_AH + i] = __float2bfloat16(0.f);
                                            sm[DEC_AL + i] = __float2bfloat16(0.f); }

    float cxr[16];
#pragma unroll
    for (int i = 0; i < 16; i++) cxr[i] = 0.f;

    float acc[2][8][4];
#pragma unroll
    for (int mi = 0; mi < 2; mi++)
#pragma unroll
        for (int j = 0; j < 8; j++)
#pragma unroll
            for (int v = 0; v < 4; v++) acc[mi][j][v] = 0.f;

    auto loadB = [&](int kc, int st) {
        const uint32_t base = sb + (DEC_B0 + st * DEC_STG) * 2;
#pragma unroll
        for (int rep = 0; rep < 4; rep++) {
            const int idx = tid + rep * 512;
            const int row = idx >> 2;
            const int qq = idx & 3;
            const uint32_t dst = base + (row * 40 + qq * 8) * 2;
            CPASYNC16(dst, g_whhH + row * 128 + kc * 32 + qq * 8);
            CPASYNC16(dst + 20480 * 2, g_whhL + row * 128 + kc * 32 + qq * 8);
        }
        CPCOMMIT();
    };

    const int i1 = (lane >> 3) & 1, i2 = lane >> 4, l7 = lane & 7;
    const uint32_t aoff = ((wm * 32 + i1 * 8 + l7) * 136 + i2 * 8) * 2;
    const uint32_t boffrel = ((wn * 16 + i2 * 8 + l7) * 40 + i1 * 8) * 2;

    loadB(0, 0);

    for (int step = 0; step < Ss; step++) {
        for (int kc = 0; kc < 4; kc++) {
            const int gi = step * 4 + kc;
            loadB((gi + 1) & 3, (gi + 1) & 1);
            CPWAIT1();
            __syncthreads();
            const uint32_t bbase = sb + (DEC_B0 + (gi & 1) * DEC_STG) * 2;
#pragma unroll
            for (int q = 0; q < 2; q++) {
                uint32_t ah[2][4], al[2][4];
                const uint32_t ka = sb + aoff + (kc * 32 + q * 16) * 2;
                LDSM4(ah[0][0], ah[0][1], ah[0][2], ah[0][3], ka);
                LDSM4(ah[1][0], ah[1][1], ah[1][2], ah[1][3], ka + 4352);
                LDSM4(al[0][0], al[0][1], al[0][2], al[0][3], ka + 17408);
                LDSM4(al[1][0], al[1][1], al[1][2], al[1][3], ka + 17408 + 4352);
#pragma unroll
                for (int pp = 0; pp < 4; pp++) {
                    uint32_t bh[2][2], bl[2][2];
                    const uint32_t kb = bbase + boffrel + q * 32 + pp * 10240;
                    LDSM4(bh[0][0], bh[0][1], bh[1][0], bh[1][1], kb);
                    LDSM4(bl[0][0], bl[0][1], bl[1][0], bl[1][1], kb + 40960);
#pragma unroll
                    for (int mi = 0; mi < 2; mi++)
#pragma unroll
                        for (int jj = 0; jj < 2; jj++) {
                            float* a = acc[mi][pp * 2 + jj];
                            MMA_BF16(a, ah[mi], bh[jj]);
                            MMA_BF16(a, ah[mi], bl[jj]);
                            MMA_BF16(a, al[mi], bh[jj]);
                        }
                }
            }
            __syncthreads();
        }
        const int last = (step == Ss - 1);
#pragma unroll
        for (int mi = 0; mi < 2; mi++)
#pragma unroll
            for (int rh = 0; rh < 2; rh++)
#pragma unroll
                for (int sub = 0; sub < 2; sub++)
#pragma unroll
                    for (int p = 0; p < 2; p++) {
                        const int rowLoc = wm * 32 + mi * 16 + rh * 8 + g;
                        const int h = wn * 16 + sub * 8 + 2 * ti + p;
                        const int grow = bm + rowLoc;
                        const int ci = mi * 8 + rh * 4 + sub * 2 + p;
                        float ig = acc[mi][0 + sub][rh * 2 + p] + Gc[(size_t)grow * 512 + h] + sbias[h];
                        float fg = acc[mi][2 + sub][rh * 2 + p] + Gc[(size_t)grow * 512 + 128 + h] + sbias[128 + h];
                        float gt = acc[mi][4 + sub][rh * 2 + p] + Gc[(size_t)grow * 512 + 256 + h] + sbias[256 + h];
                        float og = acc[mi][6 + sub][rh * 2 + p] + Gc[(size_t)grow * 512 + 384 + h] + sbias[384 + h];
                        ig = fsigm(ig); fg = fsigm(fg); gt = ftanh(gt); og = fsigm(og);
                        const float cx = fg * cxr[ci] + ig * gt;
                        cxr[ci] = cx;
                        const float hxv = og * ftanh(cx);
                        __nv_bfloat16 hh, ll;
                        splitHL(hxv, hh, ll);
                        sm[DEC_AH + rowLoc * 136 + h] = hh;
                        sm[DEC_AL + rowLoc * 136 + h] = ll;
                        if (last) {
                            const int bq = grow & 7, n = grow >> 3;
                            out[((size_t)bq * 1024 + n) * 128 + h] = hxv;
                        }
                        acc[mi][0 + sub][rh * 2 + p] = 0.f;
                        acc[mi][2 + sub][rh * 2 + p] = 0.f;
                        acc[mi][4 + sub][rh * 2 + p] = 0.f;
                        acc[mi][6 + sub][rh * 2 + p] = 0.f;
                    }
        __syncthreads();
    }
}

// ---------------------------------------------------------------------------
// Converters & small kernels
// ---------------------------------------------------------------------------
__global__ void c_splitHL(const float* __restrict__ src,
                          __nv_bfloat16* __restrict__ dH, __nv_bfloat16* __restrict__ dL,
                          int Kc, int Kp)
{
    const int row = blockIdx.y;
    const int k = blockIdx.x * 256 + threadIdx.x;
    if (k >= Kp) return;
    const float v = (k < Kc) ? src[(size_t)row * Kc + k] : 0.f;
    __nv_bfloat16 h, l;
    splitHL(v, h, l);
    dH[(size_t)row * Kp + k] = h;
    dL[(size_t)row * Kp + k] = l;
}

__global__ void c_split_x(const float* __restrict__ x)
{
    const int j = blockIdx.y;
    const int k = blockIdx.x * 256 + threadIdx.x;
    const int s = j >> 5, b = (j >> 2) & 7, f = j & 3;
    const float v = x[((size_t)(b * Ss + s) * Nn + k) * 4 + f];
    __nv_bfloat16 h, l;
    splitHL(v, h, l);
    g_xTH[(size_t)j * 1024 + k] = h;
    g_xTL[(size_t)j * 1024 + k] = l;
}

__global__ void c_wprep(const float* __restrict__ W1, const float* __restrict__ W2)
{
    const int idx = blockIdx.x * 256 + threadIdx.x;
    if (idx < 512 * 128) {
        const int gate = idx >> 7, k = idx & 127;
        const int c = k + 4;
        const float v = (gate < G3) ? W1[c * G3 + gate] : W2[c * Hh + (gate - G3)];
        __nv_bfloat16 h, l;
        splitHL(v, h, l);
        g_wcH[idx] = h;
        g_wcL[idx] = l;
    }
    if (idx < 4 * 512) {
        const int k = idx >> 9, c = idx & 511;
        g_W4[idx] = (c < G3) ? W1[k * G3 + c] : W2[k * Hh + (c - G3)];
    }
}

__global__ void k_zero()
{
    const int idx = blockIdx.x * blockDim.x + threadIdx.x;   // 1M threads
    *(float4*)(g_G + (size_t)idx * 4) = make_float4(0.f, 0.f, 0.f, 0.f);
    if (idx == 0) *(unsigned int*)&g_bar = 0u;
}

// ---------------------------------------------------------------------------
// Launch (single stream; ~12 graph nodes total)
// ---------------------------------------------------------------------------
extern "C" void kernel_launch(void* const* d_in, const int* in_sizes, int n_in,
                              void* d_out, int out_size)
{
    (void)in_sizes; (void)n_in; (void)out_size;
    const float* x   = (const float*)d_in[0];
    const float* adj = (const float*)d_in[1];
    const float* W1  = (const float*)d_in[2];
    const float* b1  = (const float*)d_in[3];
    const float* W2  = (const float*)d_in[4];
    const float* b2  = (const float*)d_in[5];
    const float* Wih = (const float*)d_in[6];
    const float* Whh = (const float*)d_in[7];
    const float* bih = (const float*)d_in[8];
    const float* bhh = (const float*)d_in[9];
    float* out = (float*)d_out;

    cudaFuncSetAttribute(gemmA<128>, cudaFuncAttributeMaxDynamicSharedMemorySize, SMEM_B128);
    cudaFuncSetAttribute(gemmA<64>, cudaFuncAttributeMaxDynamicSharedMemorySize, SMEM_B64);
    cudaFuncSetAttribute(k_enc_all, cudaFuncAttributeMaxDynamicSharedMemorySize, SMEM_STEP);
    cudaFuncSetAttribute(k_dec, cudaFuncAttributeMaxDynamicSharedMemorySize, DEC_SMEM);

    __nv_bfloat16 *pAdjH, *pAdjL, *pXH, *pXL, *pWiH, *pWiL, *pWhH, *pWhL, *pCsH, *pCsL;
    float *pAX, *pGc;
    cudaGetSymbolAddress((void**)&pAdjH, g_adjH);
    cudaGetSymbolAddress((void**)&pAdjL, g_adjL);
    cudaGetSymbolAddress((void**)&pXH, g_xTH);
    cudaGetSymbolAddress((void**)&pXL, g_xTL);
    cudaGetSymbolAddress((void**)&pWiH, g_wihH);
    cudaGetSymbolAddress((void**)&pWiL, g_wihL);
    cudaGetSymbolAddress((void**)&pWhH, g_whhH);
    cudaGetSymbolAddress((void**)&pWhL, g_whhL);
    cudaGetSymbolAddress((void**)&pCsH, g_csH);
    cudaGetSymbolAddress((void**)&pCsL, g_csL);
    cudaGetSymbolAddress((void**)&pAX, g_AX);
    cudaGetSymbolAddress((void**)&pGc, g_Gc);

    k_zero<<<4096, 256>>>();
    c_wprep<<<256, 256>>>(W1, W2);
    c_splitHL<<<dim3(4, 1024), 256>>>(adj, pAdjH, pAdjL, 1024, 1024);
    c_split_x<<<dim3(4, 1024), 256>>>(x);
    c_splitHL<<<dim3(1, 512), 256>>>(Wih, pWiH, pWiL, 128, 128);
    c_splitHL<<<dim3(1, 512), 256>>>(Whh, pWhH, pWhL, 128, 128);

    // AX = adj @ x^T (all steps)
    gemmA<64><<<dim3(16, 16), 256, SMEM_B64>>>(pAdjH, pAdjL, pXH, pXL, pAX, 1024, 1024);

    // ---------------- Encoder: ONE persistent kernel ----------------
    k_enc_all<<<dim3(16, 8), 256, SMEM_STEP>>>(b1, b2);

    // ---------------- Decoder ----------------
    gemmA<128><<<dim3(4, 128), 256, SMEM_B128>>>(pCsH, pCsL, pWiH, pWiL, pGc, 128, 512);
    k_dec<<<128, 512, DEC_SMEM>>>(pGc, bih, bhh, out);
}

// round 12
// speedup vs baseline: 1.0004x; 1.0004x over previous
#include <cuda_runtime.h>
#include <cuda_bf16.h>
#include <stdint.h>

// ---------------------------------------------------------------------------
// Problem constants
// ---------------------------------------------------------------------------
#define Bb 8
#define Ss 32
#define Nn 1024
#define Hh 128
#define NBROWS 8192
#define NBH 1048576
#define NHf 131072
#define G3 384

// ---------------------------------------------------------------------------
// Scratch (device globals; no allocation allowed). Node-major rows r = n*8+b.
// ---------------------------------------------------------------------------
__device__ __align__(16) __nv_bfloat16 g_adjH[1024 * 1024], g_adjL[1024 * 1024];
__device__ __align__(16) __nv_bfloat16 g_xTH[1024 * 1024], g_xTL[1024 * 1024];
__device__ __align__(16) __nv_bfloat16 g_hidTH[1024 * 1024], g_hidTL[1024 * 1024];
__device__ __align__(16) __nv_bfloat16 g_wcH[512 * 128], g_wcL[512 * 128];
__device__ __align__(16) __nv_bfloat16 g_wihH[512 * 128], g_wihL[512 * 128];
__device__ __align__(16) __nv_bfloat16 g_whhH[512 * 128], g_whhL[512 * 128];
__device__ __align__(16) __nv_bfloat16 g_csH[8192 * 128], g_csL[8192 * 128];

__device__ float g_W4[4 * 512];          // Wc rows 0..3, layout [k][gate]
__device__ float g_AX[1024 * 1024];
__device__ float g_G[NBROWS * 512];
__device__ float g_Gc[NBROWS * 512];
__device__ float g_csum[NBH];

// ---------------------------------------------------------------------------
// Helpers
// ---------------------------------------------------------------------------
__device__ __forceinline__ float fsigm(float x) {
    return __fdividef(1.f, 1.f + __expf(-x));
}
__device__ __forceinline__ float ftanh(float x) {
    return 1.f - __fdividef(2.f, __expf(2.f * x) + 1.f);
}

__device__ __forceinline__ uint32_t smem_u32(const void* p) {
    uint32_t a;
    asm("{ .reg .u64 t; cvta.to.shared.u64 t, %1; cvt.u32.u64 %0, t; }" : "=r"(a) : "l"(p));
    return a;
}

__device__ __forceinline__ void splitHL(float v, __nv_bfloat16& h, __nv_bfloat16& l) {
    h = __float2bfloat16(v);
    l = __float2bfloat16(v - __bfloat162float(h));
}
__device__ __forceinline__ uint32_t pack2(float v0, float v1) {
    __nv_bfloat16 a = __float2bfloat16(v0), b = __float2bfloat16(v1);
    return (uint32_t)*(unsigned short*)&a | ((uint32_t)*(unsigned short*)&b << 16);
}
__device__ __forceinline__ uint32_t pack2lo(float v0, float v1) {
    __nv_bfloat16 a = __float2bfloat16(v0);
    __nv_bfloat16 b = __float2bfloat16(v1);
    float l0 = v0 - __bfloat162float(a), l1 = v1 - __bfloat162float(b);
    __nv_bfloat16 c = __float2bfloat16(l0), d = __float2bfloat16(l1);
    return (uint32_t)*(unsigned short*)&c | ((uint32_t)*(unsigned short*)&d << 16);
}

#define MMA_BF16(c, a, b)                                                     \
    asm volatile(                                                             \
        "mma.sync.aligned.m16n8k16.row.col.f32.bf16.bf16.f32 "                \
        "{%0,%1,%2,%3},{%4,%5,%6,%7},{%8,%9},{%0,%1,%2,%3};"                  \
        : "+f"((c)[0]), "+f"((c)[1]), "+f"((c)[2]), "+f"((c)[3])              \
        : "r"((a)[0]), "r"((a)[1]), "r"((a)[2]), "r"((a)[3]),                 \
          "r"((b)[0]), "r"((b)[1]))

#define LDSM4(r0, r1, r2, r3, addr)                                           \
    asm volatile("ldmatrix.sync.aligned.m8n8.x4.shared.b16 {%0,%1,%2,%3},[%4];" \
                 : "=r"(r0), "=r"(r1), "=r"(r2), "=r"(r3) : "r"(addr))

#define CPASYNC16(s, g)                                                       \
    asm volatile("cp.async.cg.shared.global [%0], [%1], 16;" :: "r"(s), "l"(g))
#define CPCOMMIT() asm volatile("cp.async.commit_group;")
#define CPWAIT1()  asm volatile("cp.async.wait_group 1;")
#define CPWAIT0()  asm volatile("cp.async.wait_group 0;")

// ---------------------------------------------------------------------------
// 3xBF16 split GEMM (standalone, fp32 C epilogue). C = A @ B^T.
// BM=64, BN template (64/128), BK=32, 256 threads. grid = (N/BN, M/64).
// ---------------------------------------------------------------------------
template <int BN>
__global__ void __launch_bounds__(256) gemmA(
    const __nv_bfloat16* __restrict__ Ah, const __nv_bfloat16* __restrict__ Al,
    const __nv_bfloat16* __restrict__ Bh, const __nv_bfloat16* __restrict__ Bl,
    float* __restrict__ C, int K, int N)
{
    constexpr int NI = BN / 32;
    constexpr int STG = 5120 + 2 * BN * 40;

    extern __shared__ __nv_bfloat16 smem[];
    const uint32_t sb0 = smem_u32(smem);

    const int tid = threadIdx.x;
    const int lane = tid & 31;
    const int wid = tid >> 5;
    const int wm = wid >> 2;
    const int wn = wid & 3;
    const int g = lane >> 2;
    const int ti = lane & 3;

    const int bm = blockIdx.y * 64;
    const int bn = blockIdx.x * BN;

    const int arow = tid >> 2;
    const int akq = tid & 3;

    const int i1 = (lane >> 3) & 1, i2 = lane >> 4, l7 = lane & 7;
    const uint32_t aoff = ((wm * 32 + i1 * 8 + l7) * 40 + i2 * 8) * 2;
    const uint32_t boff = (5120 + (wn * (BN / 4) + i2 * 8 + l7) * 40 + i1 * 8) * 2;

    float acc[2][NI][4];
#pragma unroll
    for (int i = 0; i < 2; i++)
#pragma unroll
        for (int j = 0; j < NI; j++)
#pragma unroll
            for (int v = 0; v < 4; v++) acc[i][j][v] = 0.f;

    const int nk = K >> 5;

    auto load_stage = [&](int stage, int k0) {
        const uint32_t sb = sb0 + stage * STG * 2;
        {
            const uint32_t so = sb + (arow * 40 + akq * 8) * 2;
            CPASYNC16(so, Ah + (size_t)(bm + arow) * K + k0 + akq * 8);
            CPASYNC16(so + 2560 * 2, Al + (size_t)(bm + arow) * K + k0 + akq * 8);
        }
#pragma unroll
        for (int rep = 0; rep < BN / 64; rep++) {
            const int idx = tid + rep * 256;
            const int brow = idx >> 2;
            const int bkq = idx & 3;
            const uint32_t so = sb + (5120 + brow * 40 + bkq * 8) * 2;
            CPASYNC16(so, Bh + (size_t)(bn + brow) * K + k0 + bkq * 8);
            CPASYNC16(so + BN * 40 * 2, Bl + (size_t)(bn + brow) * K + k0 + bkq * 8);
        }
        CPCOMMIT();
    };

    load_stage(0, 0);

    for (int kt = 0; kt < nk; kt++) {
        if (kt + 1 < nk) { load_stage((kt + 1) & 1, (kt + 1) * 32); CPWAIT1(); }
        else             { CPWAIT0(); }
        __syncthreads();

        const uint32_t sb = sb0 + (kt & 1) * STG * 2;
#pragma unroll
        for (int q = 0; q < 2; q++) {
            uint32_t ah[2][4], al[2][4], bh[NI][2], bl[NI][2];
            const uint32_t ka = sb + aoff + q * 32;
            LDSM4(ah[0][0], ah[0][1], ah[0][2], ah[0][3], ka);
            LDSM4(ah[1][0], ah[1][1], ah[1][2], ah[1][3], ka + 1280);
            LDSM4(al[0][0], al[0][1], al[0][2], al[0][3], ka + 5120);
            LDSM4(al[1][0], al[1][1], al[1][2], al[1][3], ka + 5120 + 1280);
            const uint32_t kb = sb + boff + q * 32;
#pragma unroll
            for (int p = 0; p < NI / 2; p++) {
                LDSM4(bh[2 * p][0], bh[2 * p][1], bh[2 * p + 1][0], bh[2 * p + 1][1],
                      kb + p * 1280);
                LDSM4(bl[2 * p][0], bl[2 * p][1], bl[2 * p + 1][0], bl[2 * p + 1][1],
                      kb + BN * 80 + p * 1280);
            }
#pragma unroll
            for (int mi = 0; mi < 2; mi++)
#pragma unroll
                for (int ni = 0; ni < NI; ni++) {
                    MMA_BF16(acc[mi][ni], ah[mi], bh[ni]);
                    MMA_BF16(acc[mi][ni], ah[mi], bl[ni]);
                    MMA_BF16(acc[mi][ni], al[mi], bh[ni]);
                }
        }
        __syncthreads();
    }

#pragma unroll
    for (int mi = 0; mi < 2; mi++) {
        const int row = bm + wm * 32 + mi * 16 + g;
#pragma unroll
        for (int ni = 0; ni < NI; ni++) {
            const int col = bn + wn * (BN / 4) + ni * 8 + 2 * ti;
            *(float2*)(C + (size_t)row * N + col) =
                make_float2(acc[mi][ni][0], acc[mi][ni][1]);
            *(float2*)(C + (size_t)(row + 8) * N + col) =
                make_float2(acc[mi][ni][2], acc[mi][ni][3]);
        }
    }
}

#define SMEM_B128 (2 * (5120 + 2 * 128 * 40) * 2)   // 61440
#define SMEM_B64  (2 * (5120 + 2 * 64 * 40) * 2)    // 40960

// ---------------------------------------------------------------------------
// FUSED per-step encoder kernel @ 512 threads (16 warps: 2 m x 8 n).
// One CTA: AC tile (64 n-rows x 128 (b,h)-cols, K=1024, 3-pass) into SMEM,
// then G tile (64 x 512, K=128) streaming Wc from L2.
// grid = (16 n-tiles, 8 batches) = 128 CTAs. SMEM layout unchanged from R10:
// phase1 2 stages x 15360 elems; phase2 AC_hi@0, AC_lo@8704 elems,
// Wc double-buffer @17408 elems (2 x 10240). Total 75776 B.
// Warp fragment mapping = k_dec's proven 512-thread mapping.
// ---------------------------------------------------------------------------
#define STG1 15360
#define SMEM_STEP 75776

__global__ void __launch_bounds__(512) k_step()
{
    extern __shared__ __nv_bfloat16 smem[];
    const uint32_t sb0 = smem_u32(smem);

    const int tid = threadIdx.x;
    const int lane = tid & 31;
    const int wid = tid >> 5;
    const int wm = wid >> 3;              // 0..1  (32 m-rows each)
    const int wn = wid & 7;               // 0..7  (16 n-cols each)
    const int g = lane >> 2;
    const int ti = lane & 3;
    const int bm = blockIdx.x * 64;       // n-tile base
    const int b = blockIdx.y;             // batch

    const __nv_bfloat16* BH = g_hidTH + (size_t)b * 128 * 1024;
    const __nv_bfloat16* BL = g_hidTL + (size_t)b * 128 * 1024;

    const int i1 = (lane >> 3) & 1, i2 = lane >> 4, l7 = lane & 7;
    // phase-1 offsets (stage stride-40 layout)
    const uint32_t aoff = ((wm * 32 + i1 * 8 + l7) * 40 + i2 * 8) * 2;
    const uint32_t boff = (5120 + (wn * 16 + i2 * 8 + l7) * 40 + i1 * 8) * 2;
    // phase-2 offsets (AC stride-136, Wc stride-40)
    const uint32_t aoff2 = ((wm * 32 + i1 * 8 + l7) * 136 + i2 * 8) * 2;
    const uint32_t boff2 = ((wn * 16 + i2 * 8 + l7) * 40 + i1 * 8) * 2;

    float acc[2][2][4];
#pragma unroll
    for (int i = 0; i < 2; i++)
#pragma unroll
        for (int j = 0; j < 2; j++)
#pragma unroll
            for (int v = 0; v < 4; v++) acc[i][j][v] = 0.f;

    // ---------------- phase 1: AC = adj_tile @ hidT_b^T ----------------
    auto load_stage = [&](int stage, int k0) {
        const uint32_t sb = sb0 + stage * STG1 * 2;
        if (tid < 256) {
            // A: 64 rows x 32k, hi+lo (2 cp.async per thread)
            const int arow = tid >> 2, akq = tid & 3;
            const uint32_t so = sb + (arow * 40 + akq * 8) * 2;
            CPASYNC16(so, g_adjH + (size_t)(bm + arow) * 1024 + k0 + akq * 8);
            CPASYNC16(so + 2560 * 2, g_adjL + (size_t)(bm + arow) * 1024 + k0 + akq * 8);
        } else {
            // B: 128 rows x 32k, hi+lo (4 cp.async per thread)
            const int u = tid - 256;
#pragma unroll
            for (int rep = 0; rep < 2; rep++) {
                const int idx = u + rep * 256;
                const int brow = idx >> 2, bkq = idx & 3;
                const uint32_t so = sb + (5120 + brow * 40 + bkq * 8) * 2;
                CPASYNC16(so, BH + (size_t)brow * 1024 + k0 + bkq * 8);
                CPASYNC16(so + 10240, BL + (size_t)brow * 1024 + k0 + bkq * 8);
            }
        }
        CPCOMMIT();
    };

    load_stage(0, 0);

    for (int kt = 0; kt < 32; kt++) {
        if (kt + 1 < 32) { load_stage((kt + 1) & 1, (kt + 1) * 32); CPWAIT1(); }
        else             { CPWAIT0(); }
        __syncthreads();

        const uint32_t sb = sb0 + (kt & 1) * STG1 * 2;
#pragma unroll
        for (int q = 0; q < 2; q++) {
            uint32_t ah[2][4], al[2][4], bh[2][2], bl[2][2];
            const uint32_t ka = sb + aoff + q * 32;
            LDSM4(ah[0][0], ah[0][1], ah[0][2], ah[0][3], ka);
            LDSM4(ah[1][0], ah[1][1], ah[1][2], ah[1][3], ka + 1280);
            LDSM4(al[0][0], al[0][1], al[0][2], al[0][3], ka + 5120);
            LDSM4(al[1][0], al[1][1], al[1][2], al[1][3], ka + 5120 + 1280);
            const uint32_t kb = sb + boff + q * 32;
            LDSM4(bh[0][0], bh[0][1], bh[1][0], bh[1][1], kb);
            LDSM4(bl[0][0], bl[0][1], bl[1][0], bl[1][1], kb + 10240);
#pragma unroll
            for (int mi = 0; mi < 2; mi++)
#pragma unroll
                for (int ni = 0; ni < 2; ni++) {
                    MMA_BF16(acc[mi][ni], ah[mi], bh[ni]);
                    MMA_BF16(acc[mi][ni], ah[mi], bl[ni]);
                    MMA_BF16(acc[mi][ni], al[mi], bh[ni]);
                }
        }
        __syncthreads();
    }

    // ---- AC -> SMEM (split hi/lo), rows stride 136 ----
#pragma unroll
    for (int mi = 0; mi < 2; mi++) {
        const int row = wm * 32 + mi * 16 + g;
#pragma unroll
        for (int ni = 0; ni < 2; ni++) {
            const int col = wn * 16 + ni * 8 + 2 * ti;
            const uint32_t o0 = (uint32_t)(row * 136 + col) * 2;
            const uint32_t o1 = (uint32_t)((row + 8) * 136 + col) * 2;
            asm volatile("st.shared.b32 [%0], %1;" :: "r"(sb0 + o0),
                         "r"(pack2(acc[mi][ni][0], acc[mi][ni][1])));
            asm volatile("st.shared.b32 [%0], %1;" :: "r"(sb0 + 17408 + o0),
                         "r"(pack2lo(acc[mi][ni][0], acc[mi][ni][1])));
            asm volatile("st.shared.b32 [%0], %1;" :: "r"(sb0 + o1),
                         "r"(pack2(acc[mi][ni][2], acc[mi][ni][3])));
            asm volatile("st.shared.b32 [%0], %1;" :: "r"(sb0 + 17408 + o1),
                         "r"(pack2lo(acc[mi][ni][2], acc[mi][ni][3])));
        }
    }
    __syncthreads();

    // ---------------- phase 2: G = AC @ Wc^T (K=128) ----------------
    auto loadWc = [&](int idx, int st) {
        const uint32_t base = sb0 + (17408 + st * 10240) * 2;
        const int nc2 = idx >> 2, kc2 = idx & 3;
        // 128 rows x 32k hi+lo over 512 threads: 1 hi + 1 lo each
        const int row = tid >> 2, q4 = tid & 3;
        const uint32_t dst = base + (row * 40 + q4 * 8) * 2;
        CPASYNC16(dst, g_wcH + (nc2 * 128 + row) * 128 + kc2 * 32 + q4 * 8);
        CPASYNC16(dst + 5120 * 2, g_wcL + (nc2 * 128 + row) * 128 + kc2 * 32 + q4 * 8);
        CPCOMMIT();
    };

    loadWc(0, 0);

    for (int nc = 0; nc < 4; nc++) {
#pragma unroll
        for (int i = 0; i < 2; i++)
#pragma unroll
            for (int j = 0; j < 2; j++)
#pragma unroll
                for (int v = 0; v < 4; v++) acc[i][j][v] = 0.f;

        for (int kc = 0; kc < 4; kc++) {
            const int gi = nc * 4 + kc;
            if (gi < 15) { loadWc(gi + 1, (gi + 1) & 1); CPWAIT1(); }
            else         { CPWAIT0(); }
            __syncthreads();
            const uint32_t wcb = sb0 + (17408 + (gi & 1) * 10240) * 2;
#pragma unroll
            for (int q = 0; q < 2; q++) {
                uint32_t ah[2][4], al[2][4], bh[2][2], bl[2][2];
                const uint32_t ka = sb0 + aoff2 + (kc * 32 + q * 16) * 2;
                LDSM4(ah[0][0], ah[0][1], ah[0][2], ah[0][3], ka);
                LDSM4(ah[1][0], ah[1][1], ah[1][2], ah[1][3], ka + 4352);
                LDSM4(al[0][0], al[0][1], al[0][2], al[0][3], ka + 17408);
                LDSM4(al[1][0], al[1][1], al[1][2], al[1][3], ka + 17408 + 4352);
                const uint32_t kb = wcb + boff2 + q * 32;
                LDSM4(bh[0][0], bh[0][1], bh[1][0], bh[1][1], kb);
                LDSM4(bl[0][0], bl[0][1], bl[1][0], bl[1][1], kb + 10240);
#pragma unroll
                for (int mi = 0; mi < 2; mi++)
#pragma unroll
                    for (int ni = 0; ni < 2; ni++) {
                        MMA_BF16(acc[mi][ni], ah[mi], bh[ni]);
                        MMA_BF16(acc[mi][ni], ah[mi], bl[ni]);
                        MMA_BF16(acc[mi][ni], al[mi], bh[ni]);
                    }
            }
            __syncthreads();
        }

        // write G chunk (node-major rows r = n*8+b)
#pragma unroll
        for (int mi = 0; mi < 2; mi++) {
            const int n0 = bm + wm * 32 + mi * 16 + g;
#pragma unroll
            for (int ni = 0; ni < 2; ni++) {
                const int col = nc * 128 + wn * 16 + ni * 8 + 2 * ti;
                *(float2*)(g_G + ((size_t)n0 * 8 + b) * 512 + col) =
                    make_float2(acc[mi][ni][0], acc[mi][ni][1]);
                *(float2*)(g_G + ((size_t)(n0 + 8) * 8 + b) * 512 + col) =
                    make_float2(acc[mi][ni][2], acc[mi][ni][3]);
            }
        }
    }
}

// ---------------------------------------------------------------------------
// Persistent fused decoder: 32 LSTM steps in ONE launch (proven).
// grid 128 CTAs x 512 threads. Writes the (b,n,h)-permuted output directly.
// ---------------------------------------------------------------------------
#define DEC_AH 0
#define DEC_AL 8704
#define DEC_B0 17408
#define DEC_STG 40960
#define DEC_ELEMS (DEC_B0 + 2 * DEC_STG)
#define DEC_SMEM (DEC_ELEMS * 2)

__global__ void __launch_bounds__(512) k_dec(const float* __restrict__ Gc,
                                             const float* __restrict__ bih,
                                             const float* __restrict__ bhh,
                                             float* __restrict__ out)
{
    extern __shared__ __nv_bfloat16 sm[];
    __shared__ float sbias[512];
    const uint32_t sb = smem_u32(sm);

    const int tid = threadIdx.x;
    const int lane = tid & 31;
    const int wid = tid >> 5;
    const int wm = wid >> 3;
    const int wn = wid & 7;
    const int g = lane >> 2;
    const int ti = lane & 3;
    const int bm = blockIdx.x * 64;

    if (tid < 512) sbias[tid] = bih[tid] + bhh[tid];
    for (int i = tid; i < 8704; i += 512) { sm[DEC_AH + i] = __float2bfloat16(0.f);
                                            sm[DEC_AL + i] = __float2bfloat16(0.f); }

    float cxr[16];
#pragma unroll
    for (int i = 0; i < 16; i++) cxr[i] = 0.f;

    float acc[2][8][4];
#pragma unroll
    for (int mi = 0; mi < 2; mi++)
#pragma unroll
        for (int j = 0; j < 8; j++)
#pragma unroll
            for (int v = 0; v < 4; v++) acc[mi][j][v] = 0.f;

    auto loadB = [&](int kc, int st) {
        const uint32_t base = sb + (DEC_B0 + st * DEC_STG) * 2;
#pragma unroll
        for (int rep = 0; rep < 4; rep++) {
            const int idx = tid + rep * 512;
            const int row = idx >> 2;
            const int qq = idx & 3;
            const uint32_t dst = base + (row * 40 + qq * 8) * 2;
            CPASYNC16(dst, g_whhH + row * 128 + kc * 32 + qq * 8);
            CPASYNC16(dst + 20480 * 2, g_whhL + row * 128 + kc * 32 + qq * 8);
        }
        CPCOMMIT();
    };

    const int i1 = (lane >> 3) & 1, i2 = lane >> 4, l7 = lane & 7;
    const uint32_t aoff = ((wm * 32 + i1 * 8 + l7) * 136 + i2 * 8) * 2;
    const uint32_t boffrel = ((wn * 16 + i2 * 8 + l7) * 40 + i1 * 8) * 2;

    loadB(0, 0);

    for (int step = 0; step < Ss; step++) {
        for (int kc = 0; kc < 4; kc++) {
            const int gi = step * 4 + kc;
            loadB((gi + 1) & 3, (gi + 1) & 1);
            CPWAIT1();
            __syncthreads();
            const uint32_t bbase = sb + (DEC_B0 + (gi & 1) * DEC_STG) * 2;
#pragma unroll
            for (int q = 0; q < 2; q++) {
                uint32_t ah[2][4], al[2][4];
                const uint32_t ka = sb + aoff + (kc * 32 + q * 16) * 2;
                LDSM4(ah[0][0], ah[0][1], ah[0][2], ah[0][3], ka);
                LDSM4(ah[1][0], ah[1][1], ah[1][2], ah[1][3], ka + 4352);
                LDSM4(al[0][0], al[0][1], al[0][2], al[0][3], ka + 17408);
                LDSM4(al[1][0], al[1][1], al[1][2], al[1][3], ka + 17408 + 4352);
#pragma unroll
                for (int pp = 0; pp < 4; pp++) {
                    uint32_t bh[2][2], bl[2][2];
                    const uint32_t kb = bbase + boffrel + q * 32 + pp * 10240;
                    LDSM4(bh[0][0], bh[0][1], bh[1][0], bh[1][1], kb);
                    LDSM4(bl[0][0], bl[0][1], bl[1][0], bl[1][1], kb + 40960);
#pragma unroll
                    for (int mi = 0; mi < 2; mi++)
#pragma unroll
                        for (int jj = 0; jj < 2; jj++) {
                            float* a = acc[mi][pp * 2 + jj];
                            MMA_BF16(a, ah[mi], bh[jj]);
                            MMA_BF16(a, ah[mi], bl[jj]);
                            MMA_BF16(a, al[mi], bh[jj]);
                        }
                }
            }
            __syncthreads();
        }
        const int last = (step == Ss - 1);
#pragma unroll
        for (int mi = 0; mi < 2; mi++)
#pragma unroll
            for (int rh = 0; rh < 2; rh++)
#pragma unroll
                for (int sub = 0; sub < 2; sub++)
#pragma unroll
                    for (int p = 0; p < 2; p++) {
                        const int rowLoc = wm * 32 + mi * 16 + rh * 8 + g;
                        const int h = wn * 16 + sub * 8 + 2 * ti + p;
                        const int grow = bm + rowLoc;
                        const int ci = mi * 8 + rh * 4 + sub * 2 + p;
                        float ig = acc[mi][0 + sub][rh * 2 + p] + Gc[(size_t)grow * 512 + h] + sbias[h];
                        float fg = acc[mi][2 + sub][rh * 2 + p] + Gc[(size_t)grow * 512 + 128 + h] + sbias[128 + h];
                        float gt = acc[mi][4 + sub][rh * 2 + p] + Gc[(size_t)grow * 512 + 256 + h] + sbias[256 + h];
                        float og = acc[mi][6 + sub][rh * 2 + p] + Gc[(size_t)grow * 512 + 384 + h] + sbias[384 + h];
                        ig = fsigm(ig); fg = fsigm(fg); gt = ftanh(gt); og = fsigm(og);
                        const float cx = fg * cxr[ci] + ig * gt;
                        cxr[ci] = cx;
                        const float hxv = og * ftanh(cx);
                        __nv_bfloat16 hh, ll;
                        splitHL(hxv, hh, ll);
                        sm[DEC_AH + rowLoc * 136 + h] = hh;
                        sm[DEC_AL + rowLoc * 136 + h] = ll;
                        if (last) {
                            const int bq = grow & 7, n = grow >> 3;
                            out[((size_t)bq * 1024 + n) * 128 + h] = hxv;
                        }
                        acc[mi][0 + sub][rh * 2 + p] = 0.f;
                        acc[mi][2 + sub][rh * 2 + p] = 0.f;
                        acc[mi][4 + sub][rh * 2 + p] = 0.f;
                        acc[mi][6 + sub][rh * 2 + p] = 0.f;
                    }
        __syncthreads();
    }
}

// ---------------------------------------------------------------------------
// Converters & small kernels
// ---------------------------------------------------------------------------
__global__ void c_splitHL(const float* __restrict__ src,
                          __nv_bfloat16* __restrict__ dH, __nv_bfloat16* __restrict__ dL,
                          int Kc, int Kp)
{
    const int row = blockIdx.y;
    const int k = blockIdx.x * 256 + threadIdx.x;
    if (k >= Kp) return;
    const float v = (k < Kc) ? src[(size_t)row * Kc + k] : 0.f;
    __nv_bfloat16 h, l;
    splitHL(v, h, l);
    dH[(size_t)row * Kp + k] = h;
    dL[(size_t)row * Kp + k] = l;
}

__global__ void c_split_x(const float* __restrict__ x)
{
    const int j = blockIdx.y;
    const int k = blockIdx.x * 256 + threadIdx.x;
    const int s = j >> 5, b = (j >> 2) & 7, f = j & 3;
    const float v = x[((size_t)(b * Ss + s) * Nn + k) * 4 + f];
    __nv_bfloat16 h, l;
    splitHL(v, h, l);
    g_xTH[(size_t)j * 1024 + k] = h;
    g_xTL[(size_t)j * 1024 + k] = l;
}

__global__ void c_wprep(const float* __restrict__ W1, const float* __restrict__ W2)
{
    const int idx = blockIdx.x * 256 + threadIdx.x;
    if (idx < 512 * 128) {
        const int gate = idx >> 7, k = idx & 127;
        const int c = k + 4;
        const float v = (gate < G3) ? W1[c * G3 + gate] : W2[c * Hh + (gate - G3)];
        __nv_bfloat16 h, l;
        splitHL(v, h, l);
        g_wcH[idx] = h;
        g_wcL[idx] = l;
    }
    if (idx < 4 * 512) {
        const int k = idx >> 9, c = idx & 511;
        g_W4[idx] = (c < G3) ? W1[k * G3 + c] : W2[k * Hh + (c - G3)];
    }
}

__global__ void k_zero()
{
    const int idx = blockIdx.x * blockDim.x + threadIdx.x;   // 1M threads
    *(float4*)(g_G + (size_t)idx * 4) = make_float4(0.f, 0.f, 0.f, 0.f);
    g_csum[idx] = 0.f;
}

// Encoder elementwise: flat-chunk gate indexing + AX rank-4 correction,
// fused transposed hi/lo split; on last step also writes split csum.
__global__ void k_enc_elem(const float* __restrict__ b1, const float* __restrict__ b2,
                           int s, int last)
{
    __shared__ float t[32][33];
    const int b = blockIdx.x >> 7;
    const int nt = (blockIdx.x >> 2) & 31;
    const int ht = blockIdx.x & 3;
    const int n0 = nt * 32, h0 = ht * 32;
    const int hl = threadIdx.x & 31;
    const int w8 = threadIdx.x >> 5;

#pragma unroll
    for (int q = 0; q < 4; q++) {
        const int nl = w8 + q * 8;
        const int n = n0 + nl;
        const int h = h0 + hl;
        const int j = n * 128 + h;
        const int ji = j + NHf;
        const int ni = ji / G3, ci = ji - ni * G3;
        const int jo = j + 2 * NHf;
        const int no = jo / G3, co = jo - no * G3;
        const int sb4 = s * 32 + b * 4;

        float igp = g_G[(size_t)(ni * 8 + b) * 512 + ci] + b1[ci];
        float ogp = g_G[(size_t)(no * 8 + b) * 512 + co] + b1[co];
        float csp = g_G[(size_t)(n * 8 + b) * 512 + G3 + h] + b2[h];
#pragma unroll
        for (int k = 0; k < 4; k++) {
            igp += g_AX[(size_t)ni * 1024 + sb4 + k] * g_W4[k * 512 + ci];
            ogp += g_AX[(size_t)no * 1024 + sb4 + k] * g_W4[k * 512 + co];
            csp += g_AX[(size_t)n * 1024 + sb4 + k] * g_W4[k * 512 + G3 + h];
        }
        const float hn = fsigm(ogp) * ftanh(fsigm(igp) * ftanh(csp));
        const size_t co2 = (size_t)(n * 8 + b) * 128 + h;
        const float cs2 = g_csum[co2] + hn;
        g_csum[co2] = cs2;
        if (last) {
            __nv_bfloat16 ch, cl;
            splitHL(cs2, ch, cl);
            g_csH[co2] = ch;
            g_csL[co2] = cl;
        }
        t[hl][nl] = hn;
    }
    __syncthreads();
#pragma unroll
    for (int q = 0; q < 4; q++) {
        const int h2 = w8 + q * 8;
        const float v = t[h2][hl];
        __nv_bfloat16 hh, ll;
        splitHL(v, hh, ll);
        g_hidTH[(size_t)(b * 128 + h0 + h2) * 1024 + n0 + hl] = hh;
        g_hidTL[(size_t)(b * 128 + h0 + h2) * 1024 + n0 + hl] = ll;
    }
}

// ---------------------------------------------------------------------------
// Launch (single stream)
// ---------------------------------------------------------------------------
extern "C" void kernel_launch(void* const* d_in, const int* in_sizes, int n_in,
                              void* d_out, int out_size)
{
    (void)in_sizes; (void)n_in; (void)out_size;
    const float* x   = (const float*)d_in[0];
    const float* adj = (const float*)d_in[1];
    const float* W1  = (const float*)d_in[2];
    const float* b1  = (const float*)d_in[3];
    const float* W2  = (const float*)d_in[4];
    const float* b2  = (const float*)d_in[5];
    const float* Wih = (const float*)d_in[6];
    const float* Whh = (const float*)d_in[7];
    const float* bih = (const float*)d_in[8];
    const float* bhh = (const float*)d_in[9];
    float* out = (float*)d_out;

    cudaFuncSetAttribute(gemmA<128>, cudaFuncAttributeMaxDynamicSharedMemorySize, SMEM_B128);
    cudaFuncSetAttribute(gemmA<64>, cudaFuncAttributeMaxDynamicSharedMemorySize, SMEM_B64);
    cudaFuncSetAttribute(k_step, cudaFuncAttributeMaxDynamicSharedMemorySize, SMEM_STEP);
    cudaFuncSetAttribute(k_dec, cudaFuncAttributeMaxDynamicSharedMemorySize, DEC_SMEM);

    __nv_bfloat16 *pAdjH, *pAdjL, *pXH, *pXL, *pWiH, *pWiL, *pWhH, *pWhL, *pCsH, *pCsL;
    float *pAX, *pGc;
    cudaGetSymbolAddress((void**)&pAdjH, g_adjH);
    cudaGetSymbolAddress((void**)&pAdjL, g_adjL);
    cudaGetSymbolAddress((void**)&pXH, g_xTH);
    cudaGetSymbolAddress((void**)&pXL, g_xTL);
    cudaGetSymbolAddress((void**)&pWiH, g_wihH);
    cudaGetSymbolAddress((void**)&pWiL, g_wihL);
    cudaGetSymbolAddress((void**)&pWhH, g_whhH);
    cudaGetSymbolAddress((void**)&pWhL, g_whhL);
    cudaGetSymbolAddress((void**)&pCsH, g_csH);
    cudaGetSymbolAddress((void**)&pCsL, g_csL);
    cudaGetSymbolAddress((void**)&pAX, g_AX);
    cudaGetSymbolAddress((void**)&pGc, g_Gc);

    k_zero<<<4096, 256>>>();
    c_wprep<<<256, 256>>>(W1, W2);
    c_splitHL<<<dim3(4, 1024), 256>>>(adj, pAdjH, pAdjL, 1024, 1024);
    c_split_x<<<dim3(4, 1024), 256>>>(x);
    c_splitHL<<<dim3(1, 512), 256>>>(Wih, pWiH, pWiL, 128, 128);
    c_splitHL<<<dim3(1, 512), 256>>>(Whh, pWhH, pWhL, 128, 128);

    // AX = adj @ x^T (all steps)
    gemmA<64><<<dim3(16, 16), 256, SMEM_B64>>>(pAdjH, pAdjL, pXH, pXL, pAX, 1024, 1024);

    // ---------------- Encoder: 32 recurrent steps (2 kernels each) --------
    for (int s = 0; s < Ss; s++) {
        if (s) k_step<<<dim3(16, 8), 512, SMEM_STEP>>>();
        k_enc_elem<<<1024, 256>>>(b1, b2, s, s == Ss - 1);
    }

    // ---------------- Decoder ----------------
    gemmA<128><<<dim3(4, 128), 256, SMEM_B128>>>(pCsH, pCsL, pWiH, pWiL, pGc, 128, 512);
    k_dec<<<128, 512, DEC_SMEM>>>(pGc, bih, bhh, out);
}

// round 13
// speedup vs baseline: 1.0019x; 1.0015x over previous
#include <cuda_runtime.h>
#include <cuda_bf16.h>
#include <stdint.h>

// ---------------------------------------------------------------------------
// Problem constants
// ---------------------------------------------------------------------------
#define Bb 8
#define Ss 32
#define Nn 1024
#define Hh 128
#define NBROWS 8192
#define NBH 1048576
#define NHf 131072
#define G3 384

// ---------------------------------------------------------------------------
// Scratch (device globals; no allocation allowed). Node-major rows r = n*8+b.
// ---------------------------------------------------------------------------
__device__ __align__(16) __nv_bfloat16 g_adjH[1024 * 1024], g_adjL[1024 * 1024];
__device__ __align__(16) __nv_bfloat16 g_xTH[1024 * 1024], g_xTL[1024 * 1024];
__device__ __align__(16) __nv_bfloat16 g_hidTH[1024 * 1024], g_hidTL[1024 * 1024];
__device__ __align__(16) __nv_bfloat16 g_wcH[512 * 128], g_wcL[512 * 128];
__device__ __align__(16) __nv_bfloat16 g_wihH[512 * 128], g_wihL[512 * 128];
__device__ __align__(16) __nv_bfloat16 g_whhH[512 * 128], g_whhL[512 * 128];
__device__ __align__(16) __nv_bfloat16 g_csH[8192 * 128], g_csL[8192 * 128];

__device__ float g_W4[4 * 512];          // Wc rows 0..3, layout [k][gate]
__device__ float g_AX[1024 * 1024];
__device__ float g_G[NBROWS * 512];
__device__ float g_Gc[NBROWS * 512];
__device__ float g_csum[NBH];

// ---------------------------------------------------------------------------
// Helpers
// ---------------------------------------------------------------------------
__device__ __forceinline__ float fsigm(float x) {
    return __fdividef(1.f, 1.f + __expf(-x));
}
__device__ __forceinline__ float ftanh(float x) {
    return 1.f - __fdividef(2.f, __expf(2.f * x) + 1.f);
}

__device__ __forceinline__ uint32_t smem_u32(const void* p) {
    uint32_t a;
    asm("{ .reg .u64 t; cvta.to.shared.u64 t, %1; cvt.u32.u64 %0, t; }" : "=r"(a) : "l"(p));
    return a;
}

__device__ __forceinline__ void splitHL(float v, __nv_bfloat16& h, __nv_bfloat16& l) {
    h = __float2bfloat16(v);
    l = __float2bfloat16(v - __bfloat162float(h));
}
__device__ __forceinline__ uint32_t pack2(float v0, float v1) {
    __nv_bfloat16 a = __float2bfloat16(v0), b = __float2bfloat16(v1);
    return (uint32_t)*(unsigned short*)&a | ((uint32_t)*(unsigned short*)&b << 16);
}
__device__ __forceinline__ uint32_t pack2lo(float v0, float v1) {
    __nv_bfloat16 a = __float2bfloat16(v0);
    __nv_bfloat16 b = __float2bfloat16(v1);
    float l0 = v0 - __bfloat162float(a), l1 = v1 - __bfloat162float(b);
    __nv_bfloat16 c = __float2bfloat16(l0), d = __float2bfloat16(l1);
    return (uint32_t)*(unsigned short*)&c | ((uint32_t)*(unsigned short*)&d << 16);
}

#define MMA_BF16(c, a, b)                                                     \
    asm volatile(                                                             \
        "mma.sync.aligned.m16n8k16.row.col.f32.bf16.bf16.f32 "                \
        "{%0,%1,%2,%3},{%4,%5,%6,%7},{%8,%9},{%0,%1,%2,%3};"                  \
        : "+f"((c)[0]), "+f"((c)[1]), "+f"((c)[2]), "+f"((c)[3])              \
        : "r"((a)[0]), "r"((a)[1]), "r"((a)[2]), "r"((a)[3]),                 \
          "r"((b)[0]), "r"((b)[1]))

#define LDSM4(r0, r1, r2, r3, addr)                                           \
    asm volatile("ldmatrix.sync.aligned.m8n8.x4.shared.b16 {%0,%1,%2,%3},[%4];" \
                 : "=r"(r0), "=r"(r1), "=r"(r2), "=r"(r3) : "r"(addr))

#define CPASYNC16(s, g)                                                       \
    asm volatile("cp.async.cg.shared.global [%0], [%1], 16;" :: "r"(s), "l"(g))
#define CPCOMMIT() asm volatile("cp.async.commit_group;")
#define CPWAIT1()  asm volatile("cp.async.wait_group 1;")
#define CPWAIT0()  asm volatile("cp.async.wait_group 0;")

// ---------------------------------------------------------------------------
// 3xBF16 split GEMM (standalone, fp32 C epilogue). C = A @ B^T.
// BM=64, BN template (64/128), BK=32, 256 threads. grid = (N/BN, M/64).
// ---------------------------------------------------------------------------
template <int BN>
__global__ void __launch_bounds__(256) gemmA(
    const __nv_bfloat16* __restrict__ Ah, const __nv_bfloat16* __restrict__ Al,
    const __nv_bfloat16* __restrict__ Bh, const __nv_bfloat16* __restrict__ Bl,
    float* __restrict__ C, int K, int N)
{
    constexpr int NI = BN / 32;
    constexpr int STG = 5120 + 2 * BN * 40;

    extern __shared__ __nv_bfloat16 smem[];
    const uint32_t sb0 = smem_u32(smem);

    const int tid = threadIdx.x;
    const int lane = tid & 31;
    const int wid = tid >> 5;
    const int wm = wid >> 2;
    const int wn = wid & 3;
    const int g = lane >> 2;
    const int ti = lane & 3;

    const int bm = blockIdx.y * 64;
    const int bn = blockIdx.x * BN;

    const int arow = tid >> 2;
    const int akq = tid & 3;

    const int i1 = (lane >> 3) & 1, i2 = lane >> 4, l7 = lane & 7;
    const uint32_t aoff = ((wm * 32 + i1 * 8 + l7) * 40 + i2 * 8) * 2;
    const uint32_t boff = (5120 + (wn * (BN / 4) + i2 * 8 + l7) * 40 + i1 * 8) * 2;

    float acc[2][NI][4];
#pragma unroll
    for (int i = 0; i < 2; i++)
#pragma unroll
        for (int j = 0; j < NI; j++)
#pragma unroll
            for (int v = 0; v < 4; v++) acc[i][j][v] = 0.f;

    const int nk = K >> 5;

    auto load_stage = [&](int stage, int k0) {
        const uint32_t sb = sb0 + stage * STG * 2;
        {
            const uint32_t so = sb + (arow * 40 + akq * 8) * 2;
            CPASYNC16(so, Ah + (size_t)(bm + arow) * K + k0 + akq * 8);
            CPASYNC16(so + 2560 * 2, Al + (size_t)(bm + arow) * K + k0 + akq * 8);
        }
#pragma unroll
        for (int rep = 0; rep < BN / 64; rep++) {
            const int idx = tid + rep * 256;
            const int brow = idx >> 2;
            const int bkq = idx & 3;
            const uint32_t so = sb + (5120 + brow * 40 + bkq * 8) * 2;
            CPASYNC16(so, Bh + (size_t)(bn + brow) * K + k0 + bkq * 8);
            CPASYNC16(so + BN * 40 * 2, Bl + (size_t)(bn + brow) * K + k0 + bkq * 8);
        }
        CPCOMMIT();
    };

    load_stage(0, 0);

    for (int kt = 0; kt < nk; kt++) {
        if (kt + 1 < nk) { load_stage((kt + 1) & 1, (kt + 1) * 32); CPWAIT1(); }
        else             { CPWAIT0(); }
        __syncthreads();

        const uint32_t sb = sb0 + (kt & 1) * STG * 2;
#pragma unroll
        for (int q = 0; q < 2; q++) {
            uint32_t ah[2][4], al[2][4], bh[NI][2], bl[NI][2];
            const uint32_t ka = sb + aoff + q * 32;
            LDSM4(ah[0][0], ah[0][1], ah[0][2], ah[0][3], ka);
            LDSM4(ah[1][0], ah[1][1], ah[1][2], ah[1][3], ka + 1280);
            LDSM4(al[0][0], al[0][1], al[0][2], al[0][3], ka + 5120);
            LDSM4(al[1][0], al[1][1], al[1][2], al[1][3], ka + 5120 + 1280);
            const uint32_t kb = sb + boff + q * 32;
#pragma unroll
            for (int p = 0; p < NI / 2; p++) {
                LDSM4(bh[2 * p][0], bh[2 * p][1], bh[2 * p + 1][0], bh[2 * p + 1][1],
                      kb + p * 1280);
                LDSM4(bl[2 * p][0], bl[2 * p][1], bl[2 * p + 1][0], bl[2 * p + 1][1],
                      kb + BN * 80 + p * 1280);
            }
#pragma unroll
            for (int mi = 0; mi < 2; mi++)
#pragma unroll
                for (int ni = 0; ni < NI; ni++) {
                    MMA_BF16(acc[mi][ni], ah[mi], bh[ni]);
                    MMA_BF16(acc[mi][ni], ah[mi], bl[ni]);
                    MMA_BF16(acc[mi][ni], al[mi], bh[ni]);
                }
        }
        __syncthreads();
    }

#pragma unroll
    for (int mi = 0; mi < 2; mi++) {
        const int row = bm + wm * 32 + mi * 16 + g;
#pragma unroll
        for (int ni = 0; ni < NI; ni++) {
            const int col = bn + wn * (BN / 4) + ni * 8 + 2 * ti;
            *(float2*)(C + (size_t)row * N + col) =
                make_float2(acc[mi][ni][0], acc[mi][ni][1]);
            *(float2*)(C + (size_t)(row + 8) * N + col) =
                make_float2(acc[mi][ni][2], acc[mi][ni][3]);
        }
    }
}

#define SMEM_B128 (2 * (5120 + 2 * 128 * 40) * 2)   // 61440
#define SMEM_B64  (2 * (5120 + 2 * 64 * 40) * 2)    // 40960

// ---------------------------------------------------------------------------
// FUSED per-step encoder kernel @ 512 threads (16 warps: 2 m x 8 n).
// One CTA: AC tile (64 n-rows x 128 (b,h)-cols, K=1024, 3-pass) into SMEM,
// then G tile (64 x 512, K=128) streaming Wc from L2.
// grid = (16 n-tiles, 8 batches) = 128 CTAs. SMEM layout unchanged from R10:
// phase1 2 stages x 15360 elems; phase2 AC_hi@0, AC_lo@8704 elems,
// Wc double-buffer @17408 elems (2 x 10240). Total 75776 B.
// Warp fragment mapping = k_dec's proven 512-thread mapping.
// ---------------------------------------------------------------------------
#define STG1 15360
#define SMEM_STEP 75776

__global__ void __launch_bounds__(512) k_step()
{
    extern __shared__ __nv_bfloat16 smem[];
    const uint32_t sb0 = smem_u32(smem);

    const int tid = threadIdx.x;
    const int lane = tid & 31;
    const int wid = tid >> 5;
    const int wm = wid >> 3;              // 0..1  (32 m-rows each)
    const int wn = wid & 7;               // 0..7  (16 n-cols each)
    const int g = lane >> 2;
    const int ti = lane & 3;
    const int bm = blockIdx.x * 64;       // n-tile base
    const int b = blockIdx.y;             // batch

    const __nv_bfloat16* BH = g_hidTH + (size_t)b * 128 * 1024;
    const __nv_bfloat16* BL = g_hidTL + (size_t)b * 128 * 1024;

    const int i1 = (lane >> 3) & 1, i2 = lane >> 4, l7 = lane & 7;
    // phase-1 offsets (stage stride-40 layout)
    const uint32_t aoff = ((wm * 32 + i1 * 8 + l7) * 40 + i2 * 8) * 2;
    const uint32_t boff = (5120 + (wn * 16 + i2 * 8 + l7) * 40 + i1 * 8) * 2;
    // phase-2 offsets (AC stride-136, Wc stride-40)
    const uint32_t aoff2 = ((wm * 32 + i1 * 8 + l7) * 136 + i2 * 8) * 2;
    const uint32_t boff2 = ((wn * 16 + i2 * 8 + l7) * 40 + i1 * 8) * 2;

    float acc[2][2][4];
#pragma unroll
    for (int i = 0; i < 2; i++)
#pragma unroll
        for (int j = 0; j < 2; j++)
#pragma unroll
            for (int v = 0; v < 4; v++) acc[i][j][v] = 0.f;

    // ---------------- phase 1: AC = adj_tile @ hidT_b^T ----------------
    auto load_stage = [&](int stage, int k0) {
        const uint32_t sb = sb0 + stage * STG1 * 2;
        if (tid < 256) {
            // A: 64 rows x 32k, hi+lo (2 cp.async per thread)
            const int arow = tid >> 2, akq = tid & 3;
            const uint32_t so = sb + (arow * 40 + akq * 8) * 2;
            CPASYNC16(so, g_adjH + (size_t)(bm + arow) * 1024 + k0 + akq * 8);
            CPASYNC16(so + 2560 * 2, g_adjL + (size_t)(bm + arow) * 1024 + k0 + akq * 8);
        } else {
            // B: 128 rows x 32k, hi+lo (4 cp.async per thread)
            const int u = tid - 256;
#pragma unroll
            for (int rep = 0; rep < 2; rep++) {
                const int idx = u + rep * 256;
                const int brow = idx >> 2, bkq = idx & 3;
                const uint32_t so = sb + (5120 + brow * 40 + bkq * 8) * 2;
                CPASYNC16(so, BH + (size_t)brow * 1024 + k0 + bkq * 8);
                CPASYNC16(so + 10240, BL + (size_t)brow * 1024 + k0 + bkq * 8);
            }
        }
        CPCOMMIT();
    };

    load_stage(0, 0);

    for (int kt = 0; kt < 32; kt++) {
        if (kt + 1 < 32) { load_stage((kt + 1) & 1, (kt + 1) * 32); CPWAIT1(); }
        else             { CPWAIT0(); }
        __syncthreads();

        const uint32_t sb = sb0 + (kt & 1) * STG1 * 2;
#pragma unroll
        for (int q = 0; q < 2; q++) {
            uint32_t ah[2][4], al[2][4], bh[2][2], bl[2][2];
            const uint32_t ka = sb + aoff + q * 32;
            LDSM4(ah[0][0], ah[0][1], ah[0][2], ah[0][3], ka);
            LDSM4(ah[1][0], ah[1][1], ah[1][2], ah[1][3], ka + 1280);
            LDSM4(al[0][0], al[0][1], al[0][2], al[0][3], ka + 5120);
            LDSM4(al[1][0], al[1][1], al[1][2], al[1][3], ka + 5120 + 1280);
            const uint32_t kb = sb + boff + q * 32;
            LDSM4(bh[0][0], bh[0][1], bh[1][0], bh[1][1], kb);
            LDSM4(bl[0][0], bl[0][1], bl[1][0], bl[1][1], kb + 10240);
#pragma unroll
            for (int mi = 0; mi < 2; mi++)
#pragma unroll
                for (int ni = 0; ni < 2; ni++) {
                    MMA_BF16(acc[mi][ni], ah[mi], bh[ni]);
                    MMA_BF16(acc[mi][ni], ah[mi], bl[ni]);
                    MMA_BF16(acc[mi][ni], al[mi], bh[ni]);
                }
        }
        __syncthreads();
    }

    // ---- AC -> SMEM (split hi/lo), rows stride 136 ----
#pragma unroll
    for (int mi = 0; mi < 2; mi++) {
        const int row = wm * 32 + mi * 16 + g;
#pragma unroll
        for (int ni = 0; ni < 2; ni++) {
            const int col = wn * 16 + ni * 8 + 2 * ti;
            const uint32_t o0 = (uint32_t)(row * 136 + col) * 2;
            const uint32_t o1 = (uint32_t)((row + 8) * 136 + col) * 2;
            asm volatile("st.shared.b32 [%0], %1;" :: "r"(sb0 + o0),
                         "r"(pack2(acc[mi][ni][0], acc[mi][ni][1])));
            asm volatile("st.shared.b32 [%0], %1;" :: "r"(sb0 + 17408 + o0),
                         "r"(pack2lo(acc[mi][ni][0], acc[mi][ni][1])));
            asm volatile("st.shared.b32 [%0], %1;" :: "r"(sb0 + o1),
                         "r"(pack2(acc[mi][ni][2], acc[mi][ni][3])));
            asm volatile("st.shared.b32 [%0], %1;" :: "r"(sb0 + 17408 + o1),
                         "r"(pack2lo(acc[mi][ni][2], acc[mi][ni][3])));
        }
    }
    __syncthreads();

    // ---------------- phase 2: G = AC @ Wc^T (K=128) ----------------
    auto loadWc = [&](int idx, int st) {
        const uint32_t base = sb0 + (17408 + st * 10240) * 2;
        const int nc2 = idx >> 2, kc2 = idx & 3;
        // 128 rows x 32k hi+lo over 512 threads: 1 hi + 1 lo each
        const int row = tid >> 2, q4 = tid & 3;
        const uint32_t dst = base + (row * 40 + q4 * 8) * 2;
        CPASYNC16(dst, g_wcH + (nc2 * 128 + row) * 128 + kc2 * 32 + q4 * 8);
        CPASYNC16(dst + 5120 * 2, g_wcL + (nc2 * 128 + row) * 128 + kc2 * 32 + q4 * 8);
        CPCOMMIT();
    };

    loadWc(0, 0);

    for (int nc = 0; nc < 4; nc++) {
#pragma unroll
        for (int i = 0; i < 2; i++)
#pragma unroll
            for (int j = 0; j < 2; j++)
#pragma unroll
                for (int v = 0; v < 4; v++) acc[i][j][v] = 0.f;

        for (int kc = 0; kc < 4; kc++) {
            const int gi = nc * 4 + kc;
            if (gi < 15) { loadWc(gi + 1, (gi + 1) & 1); CPWAIT1(); }
            else         { CPWAIT0(); }
            __syncthreads();
            const uint32_t wcb = sb0 + (17408 + (gi & 1) * 10240) * 2;
#pragma unroll
            for (int q = 0; q < 2; q++) {
                uint32_t ah[2][4], al[2][4], bh[2][2], bl[2][2];
                const uint32_t ka = sb0 + aoff2 + (kc * 32 + q * 16) * 2;
                LDSM4(ah[0][0], ah[0][1], ah[0][2], ah[0][3], ka);
                LDSM4(ah[1][0], ah[1][1], ah[1][2], ah[1][3], ka + 4352);
                LDSM4(al[0][0], al[0][1], al[0][2], al[0][3], ka + 17408);
                LDSM4(al[1][0], al[1][1], al[1][2], al[1][3], ka + 17408 + 4352);
                const uint32_t kb = wcb + boff2 + q * 32;
                LDSM4(bh[0][0], bh[0][1], bh[1][0], bh[1][1], kb);
                LDSM4(bl[0][0], bl[0][1], bl[1][0], bl[1][1], kb + 10240);
#pragma unroll
                for (int mi = 0; mi < 2; mi++)
#pragma unroll
                    for (int ni = 0; ni < 2; ni++) {
                        MMA_BF16(acc[mi][ni], ah[mi], bh[ni]);
                        MMA_BF16(acc[mi][ni], ah[mi], bl[ni]);
                        MMA_BF16(acc[mi][ni], al[mi], bh[ni]);
                    }
            }
            __syncthreads();
        }

        // write G chunk (node-major rows r = n*8+b)
#pragma unroll
        for (int mi = 0; mi < 2; mi++) {
            const int n0 = bm + wm * 32 + mi * 16 + g;
#pragma unroll
            for (int ni = 0; ni < 2; ni++) {
                const int col = nc * 128 + wn * 16 + ni * 8 + 2 * ti;
                *(float2*)(g_G + ((size_t)n0 * 8 + b) * 512 + col) =
                    make_float2(acc[mi][ni][0], acc[mi][ni][1]);
                *(float2*)(g_G + ((size_t)(n0 + 8) * 8 + b) * 512 + col) =
                    make_float2(acc[mi][ni][2], acc[mi][ni][3]);
            }
        }
    }
}

// ---------------------------------------------------------------------------
// Persistent fused decoder: 32 LSTM steps in ONE launch (proven).
// grid 128 CTAs x 512 threads. Writes the (b,n,h)-permuted output directly.
// ---------------------------------------------------------------------------
#define DEC_AH 0
#define DEC_AL 8704
#define DEC_B0 17408
#define DEC_STG 40960
#define DEC_ELEMS (DEC_B0 + 2 * DEC_STG)
#define DEC_SMEM (DEC_ELEMS * 2)

__global__ void __launch_bounds__(512) k_dec(const float* __restrict__ Gc,
                                             const float* __restrict__ bih,
                                             const float* __restrict__ bhh,
                                             float* __restrict__ out)
{
    extern __shared__ __nv_bfloat16 sm[];
    __shared__ float sbias[512];
    const uint32_t sb = smem_u32(sm);

    const int tid = threadIdx.x;
    const int lane = tid & 31;
    const int wid = tid >> 5;
    const int wm = wid >> 3;
    const int wn = wid & 7;
    const int g = lane >> 2;
    const int ti = lane & 3;
    const int bm = blockIdx.x * 64;

    if (tid < 512) sbias[tid] = bih[tid] + bhh[tid];
    for (int i = tid; i < 8704; i += 512) { sm[DEC_AH + i] = __float2bfloat16(0.f);
                                            sm[DEC_AL + i] = __float2bfloat16(0.f); }

    float cxr[16];
#pragma unroll
    for (int i = 0; i < 16; i++) cxr[i] = 0.f;

    float acc[2][8][4];
#pragma unroll
    for (int mi = 0; mi < 2; mi++)
#pragma unroll
        for (int j = 0; j < 8; j++)
#pragma unroll
            for (int v = 0; v < 4; v++) acc[mi][j][v] = 0.f;

    auto loadB = [&](int kc, int st) {
        const uint32_t base = sb + (DEC_B0 + st * DEC_STG) * 2;
#pragma unroll
        for (int rep = 0; rep < 4; rep++) {
            const int idx = tid + rep * 512;
            const int row = idx >> 2;
            const int qq = idx & 3;
            const uint32_t dst = base + (row * 40 + qq * 8) * 2;
            CPASYNC16(dst, g_whhH + row * 128 + kc * 32 + qq * 8);
            CPASYNC16(dst + 20480 * 2, g_whhL + row * 128 + kc * 32 + qq * 8);
        }
        CPCOMMIT();
    };

    const int i1 = (lane >> 3) & 1, i2 = lane >> 4, l7 = lane & 7;
    const uint32_t aoff = ((wm * 32 + i1 * 8 + l7) * 136 + i2 * 8) * 2;
    const uint32_t boffrel = ((wn * 16 + i2 * 8 + l7) * 40 + i1 * 8) * 2;

    loadB(0, 0);

    for (int step = 0; step < Ss; step++) {
        for (int kc = 0; kc < 4; kc++) {
            const int gi = step * 4 + kc;
            loadB((gi + 1) & 3, (gi + 1) & 1);
            CPWAIT1();
            __syncthreads();
            const uint32_t bbase = sb + (DEC_B0 + (gi & 1) * DEC_STG) * 2;
#pragma unroll
            for (int q = 0; q < 2; q++) {
                uint32_t ah[2][4], al[2][4];
                const uint32_t ka = sb + aoff + (kc * 32 + q * 16) * 2;
                LDSM4(ah[0][0], ah[0][1], ah[0][2], ah[0][3], ka);
                LDSM4(ah[1][0], ah[1][1], ah[1][2], ah[1][3], ka + 4352);
                LDSM4(al[0][0], al[0][1], al[0][2], al[0][3], ka + 17408);
                LDSM4(al[1][0], al[1][1], al[1][2], al[1][3], ka + 17408 + 4352);
#pragma unroll
                for (int pp = 0; pp < 4; pp++) {
                    uint32_t bh[2][2], bl[2][2];
                    const uint32_t kb = bbase + boffrel + q * 32 + pp * 10240;
                    LDSM4(bh[0][0], bh[0][1], bh[1][0], bh[1][1], kb);
                    LDSM4(bl[0][0], bl[0][1], bl[1][0], bl[1][1], kb + 40960);
#pragma unroll
                    for (int mi = 0; mi < 2; mi++)
#pragma unroll
                        for (int jj = 0; jj < 2; jj++) {
                            float* a = acc[mi][pp * 2 + jj];
                            MMA_BF16(a, ah[mi], bh[jj]);
                            MMA_BF16(a, ah[mi], bl[jj]);
                            MMA_BF16(a, al[mi], bh[jj]);
                        }
                }
            }
            __syncthreads();
        }
        const int last = (step == Ss - 1);
#pragma unroll
        for (int mi = 0; mi < 2; mi++)
#pragma unroll
            for (int rh = 0; rh < 2; rh++)
#pragma unroll
                for (int sub = 0; sub < 2; sub++)
#pragma unroll
                    for (int p = 0; p < 2; p++) {
                        const int rowLoc = wm * 32 + mi * 16 + rh * 8 + g;
                        const int h = wn * 16 + sub * 8 + 2 * ti + p;
                        const int grow = bm + rowLoc;
                        const int ci = mi * 8 + rh * 4 + sub * 2 + p;
                        float ig = acc[mi][0 + sub][rh * 2 + p] + Gc[(size_t)grow * 512 + h] + sbias[h];
                        float fg = acc[mi][2 + sub][rh * 2 + p] + Gc[(size_t)grow * 512 + 128 + h] + sbias[128 + h];
                        float gt = acc[mi][4 + sub][rh * 2 + p] + Gc[(size_t)grow * 512 + 256 + h] + sbias[256 + h];
                        float og = acc[mi][6 + sub][rh * 2 + p] + Gc[(size_t)grow * 512 + 384 + h] + sbias[384 + h];
                        ig = fsigm(ig); fg = fsigm(fg); gt = ftanh(gt); og = fsigm(og);
                        const float cx = fg * cxr[ci] + ig * gt;
                        cxr[ci] = cx;
                        const float hxv = og * ftanh(cx);
                        __nv_bfloat16 hh, ll;
                        splitHL(hxv, hh, ll);
                        sm[DEC_AH + rowLoc * 136 + h] = hh;
                        sm[DEC_AL + rowLoc * 136 + h] = ll;
                        if (last) {
                            const int bq = grow & 7, n = grow >> 3;
                            out[((size_t)bq * 1024 + n) * 128 + h] = hxv;
                        }
                        acc[mi][0 + sub][rh * 2 + p] = 0.f;
                        acc[mi][2 + sub][rh * 2 + p] = 0.f;
                        acc[mi][4 + sub][rh * 2 + p] = 0.f;
                        acc[mi][6 + sub][rh * 2 + p] = 0.f;
                    }
        __syncthreads();
    }
}

// ---------------------------------------------------------------------------
// Converters & small kernels
// ---------------------------------------------------------------------------
__global__ void c_splitHL(const float* __restrict__ src,
                          __nv_bfloat16* __restrict__ dH, __nv_bfloat16* __restrict__ dL,
                          int Kc, int Kp)
{
    const int row = blockIdx.y;
    const int k = blockIdx.x * 256 + threadIdx.x;
    if (k >= Kp) return;
    const float v = (k < Kc) ? src[(size_t)row * Kc + k] : 0.f;
    __nv_bfloat16 h, l;
    splitHL(v, h, l);
    dH[(size_t)row * Kp + k] = h;
    dL[(size_t)row * Kp + k] = l;
}

__global__ void c_split_x(const float* __restrict__ x)
{
    const int j = blockIdx.y;
    const int k = blockIdx.x * 256 + threadIdx.x;
    const int s = j >> 5, b = (j >> 2) & 7, f = j & 3;
    const float v = x[((size_t)(b * Ss + s) * Nn + k) * 4 + f];
    __nv_bfloat16 h, l;
    splitHL(v, h, l);
    g_xTH[(size_t)j * 1024 + k] = h;
    g_xTL[(size_t)j * 1024 + k] = l;
}

__global__ void c_wprep(const float* __restrict__ W1, const float* __restrict__ W2)
{
    const int idx = blockIdx.x * 256 + threadIdx.x;
    if (idx < 512 * 128) {
        const int gate = idx >> 7, k = idx & 127;
        const int c = k + 4;
        const float v = (gate < G3) ? W1[c * G3 + gate] : W2[c * Hh + (gate - G3)];
        __nv_bfloat16 h, l;
        splitHL(v, h, l);
        g_wcH[idx] = h;
        g_wcL[idx] = l;
    }
    if (idx < 4 * 512) {
        const int k = idx >> 9, c = idx & 511;
        g_W4[idx] = (c < G3) ? W1[k * G3 + c] : W2[k * Hh + (c - G3)];
    }
}

__global__ void k_zero()
{
    const int idx = blockIdx.x * blockDim.x + threadIdx.x;   // 1M threads
    *(float4*)(g_G + (size_t)idx * 4) = make_float4(0.f, 0.f, 0.f, 0.f);
    g_csum[idx] = 0.f;
}

// Encoder elementwise: flat-chunk gate indexing + AX rank-4 correction,
// fused transposed hi/lo split; on last step also writes split csum.
__global__ void k_enc_elem(const float* __restrict__ b1, const float* __restrict__ b2,
                           int s, int last)
{
    __shared__ float t[32][33];
    const int b = blockIdx.x >> 7;
    const int nt = (blockIdx.x >> 2) & 31;
    const int ht = blockIdx.x & 3;
    const int n0 = nt * 32, h0 = ht * 32;
    const int hl = threadIdx.x & 31;
    const int w8 = threadIdx.x >> 5;

#pragma unroll
    for (int q = 0; q < 4; q++) {
        const int nl = w8 + q * 8;
        const int n = n0 + nl;
        const int h = h0 + hl;
        const int j = n * 128 + h;
        const int ji = j + NHf;
        const int ni = ji / G3, ci = ji - ni * G3;
        const int jo = j + 2 * NHf;
        const int no = jo / G3, co = jo - no * G3;
        const int sb4 = s * 32 + b * 4;

        float igp = g_G[(size_t)(ni * 8 + b) * 512 + ci] + b1[ci];
        float ogp = g_G[(size_t)(no * 8 + b) * 512 + co] + b1[co];
        float csp = g_G[(size_t)(n * 8 + b) * 512 + G3 + h] + b2[h];
#pragma unroll
        for (int k = 0; k < 4; k++) {
            igp += g_AX[(size_t)ni * 1024 + sb4 + k] * g_W4[k * 512 + ci];
            ogp += g_AX[(size_t)no * 1024 + sb4 + k] * g_W4[k * 512 + co];
            csp += g_AX[(size_t)n * 1024 + sb4 + k] * g_W4[k * 512 + G3 + h];
        }
        const float hn = fsigm(ogp) * ftanh(fsigm(igp) * ftanh(csp));
        const size_t co2 = (size_t)(n * 8 + b) * 128 + h;
        const float cs2 = g_csum[co2] + hn;
        g_csum[co2] = cs2;
        if (last) {
            __nv_bfloat16 ch, cl;
            splitHL(cs2, ch, cl);
            g_csH[co2] = ch;
            g_csL[co2] = cl;
        }
        t[hl][nl] = hn;
    }
    __syncthreads();
#pragma unroll
    for (int q = 0; q < 4; q++) {
        const int h2 = w8 + q * 8;
        const float v = t[h2][hl];
        __nv_bfloat16 hh, ll;
        splitHL(v, hh, ll);
        g_hidTH[(size_t)(b * 128 + h0 + h2) * 1024 + n0 + hl] = hh;
        g_hidTL[(size_t)(b * 128 + h0 + h2) * 1024 + n0 + hl] = ll;
    }
}

// ---------------------------------------------------------------------------
// Launch (single stream)
// ---------------------------------------------------------------------------
extern "C" void kernel_launch(void* const* d_in, const int* in_sizes, int n_in,
                              void* d_out, int out_size)
{
    (void)in_sizes; (void)n_in; (void)out_size;
    const float* x   = (const float*)d_in[0];
    const float* adj = (const float*)d_in[1];
    const float* W1  = (const float*)d_in[2];
    const float* b1  = (const float*)d_in[3];
    const float* W2  = (const float*)d_in[4];
    const float* b2  = (const float*)d_in[5];
    const float* Wih = (const float*)d_in[6];
    const float* Whh = (const float*)d_in[7];
    const float* bih = (const float*)d_in[8];
    const float* bhh = (const float*)d_in[9];
    float* out = (float*)d_out;

    cudaFuncSetAttribute(gemmA<128>, cudaFuncAttributeMaxDynamicSharedMemorySize, SMEM_B128);
    cudaFuncSetAttribute(gemmA<64>, cudaFuncAttributeMaxDynamicSharedMemorySize, SMEM_B64);
    cudaFuncSetAttribute(k_step, cudaFuncAttributeMaxDynamicSharedMemorySize, SMEM_STEP);
    cudaFuncSetAttribute(k_dec, cudaFuncAttributeMaxDynamicSharedMemorySize, DEC_SMEM);

    __nv_bfloat16 *pAdjH, *pAdjL, *pXH, *pXL, *pWiH, *pWiL, *pWhH, *pWhL, *pCsH, *pCsL;
    float *pAX, *pGc;
    cudaGetSymbolAddress((void**)&pAdjH, g_adjH);
    cudaGetSymbolAddress((void**)&pAdjL, g_adjL);
    cudaGetSymbolAddress((void**)&pXH, g_xTH);
    cudaGetSymbolAddress((void**)&pXL, g_xTL);
    cudaGetSymbolAddress((void**)&pWiH, g_wihH);
    cudaGetSymbolAddress((void**)&pWiL, g_wihL);
    cudaGetSymbolAddress((void**)&pWhH, g_whhH);
    cudaGetSymbolAddress((void**)&pWhL, g_whhL);
    cudaGetSymbolAddress((void**)&pCsH, g_csH);
    cudaGetSymbolAddress((void**)&pCsL, g_csL);
    cudaGetSymbolAddress((void**)&pAX, g_AX);
    cudaGetSymbolAddress((void**)&pGc, g_Gc);

    k_zero<<<4096, 256>>>();
    c_wprep<<<256, 256>>>(W1, W2);
    c_splitHL<<<dim3(4, 1024), 256>>>(adj, pAdjH, pAdjL, 1024, 1024);
    c_split_x<<<dim3(4, 1024), 256>>>(x);
    c_splitHL<<<dim3(1, 512), 256>>>(Wih, pWiH, pWiL, 128, 128);
    c_splitHL<<<dim3(1, 512), 256>>>(Whh, pWhH, pWhL, 128, 128);

    // AX = adj @ x^T (all steps)
    gemmA<64><<<dim3(16, 16), 256, SMEM_B64>>>(pAdjH, pAdjL, pXH, pXL, pAX, 1024, 1024);

    // ---------------- Encoder: 32 recurrent steps (2 kernels each) --------
    for (int s = 0; s < Ss; s++) {
        if (s) k_step<<<dim3(16, 8), 512, SMEM_STEP>>>();
        k_enc_elem<<<1024, 256>>>(b1, b2, s, s == Ss - 1);
    }

    // ---------------- Decoder ----------------
    gemmA<128><<<dim3(4, 128), 256, SMEM_B128>>>(pCsH, pCsL, pWiH, pWiL, pGc, 128, 512);
    k_dec<<<128, 512, DEC_SMEM>>>(pGc, bih, bhh, out);
}

// round 15
// speedup vs baseline: 1.0897x; 1.0876x over previous
#include <cuda_runtime.h>
#include <cuda_bf16.h>
#include <stdint.h>

// ---------------------------------------------------------------------------
// Problem constants
// ---------------------------------------------------------------------------
#define Bb 8
#define Ss 32
#define Nn 1024
#define Hh 128
#define NBROWS 8192
#define NBH 1048576
#define NHf 131072
#define G3 384

// ---------------------------------------------------------------------------
// Scratch (device globals; no allocation allowed). Node-major rows r = n*8+b.
// ---------------------------------------------------------------------------
__device__ __align__(16) __nv_bfloat16 g_adjH[1024 * 1024], g_adjL[1024 * 1024];
__device__ __align__(16) __nv_bfloat16 g_xTH[1024 * 1024], g_xTL[1024 * 1024];
__device__ __align__(16) __nv_bfloat16 g_hidTH[1024 * 1024], g_hidTL[1024 * 1024];
__device__ __align__(16) __nv_bfloat16 g_wcH[512 * 128], g_wcL[512 * 128];
__device__ __align__(16) __nv_bfloat16 g_wihH[512 * 128], g_wihL[512 * 128];
__device__ __align__(16) __nv_bfloat16 g_whhH[512 * 128], g_whhL[512 * 128];
__device__ __align__(16) __nv_bfloat16 g_csH[8192 * 128], g_csL[8192 * 128];

__device__ float g_W4[4 * 512];          // Wc rows 0..3, layout [k][gate]
__device__ float g_AX[1024 * 1024];
__device__ float g_G[NBROWS * 512];
__device__ float g_Gc[NBROWS * 512];
__device__ float g_csum[NBH];

// ---------------------------------------------------------------------------
// Helpers
// ---------------------------------------------------------------------------
__device__ __forceinline__ float fsigm(float x) {
    return __fdividef(1.f, 1.f + __expf(-x));
}
__device__ __forceinline__ float ftanh(float x) {
    return 1.f - __fdividef(2.f, __expf(2.f * x) + 1.f);
}

__device__ __forceinline__ uint32_t smem_u32(const void* p) {
    uint32_t a;
    asm("{ .reg .u64 t; cvta.to.shared.u64 t, %1; cvt.u32.u64 %0, t; }" : "=r"(a) : "l"(p));
    return a;
}

__device__ __forceinline__ void splitHL(float v, __nv_bfloat16& h, __nv_bfloat16& l) {
    h = __float2bfloat16(v);
    l = __float2bfloat16(v - __bfloat162float(h));
}
__device__ __forceinline__ uint32_t pack2(float v0, float v1) {
    __nv_bfloat16 a = __float2bfloat16(v0), b = __float2bfloat16(v1);
    return (uint32_t)*(unsigned short*)&a | ((uint32_t)*(unsigned short*)&b << 16);
}
__device__ __forceinline__ uint32_t pack2lo(float v0, float v1) {
    __nv_bfloat16 a = __float2bfloat16(v0);
    __nv_bfloat16 b = __float2bfloat16(v1);
    float l0 = v0 - __bfloat162float(a), l1 = v1 - __bfloat162float(b);
    __nv_bfloat16 c = __float2bfloat16(l0), d = __float2bfloat16(l1);
    return (uint32_t)*(unsigned short*)&c | ((uint32_t)*(unsigned short*)&d << 16);
}

#define MMA_BF16(c, a, b)                                                     \
    asm volatile(                                                             \
        "mma.sync.aligned.m16n8k16.row.col.f32.bf16.bf16.f32 "                \
        "{%0,%1,%2,%3},{%4,%5,%6,%7},{%8,%9},{%0,%1,%2,%3};"                  \
        : "+f"((c)[0]), "+f"((c)[1]), "+f"((c)[2]), "+f"((c)[3])              \
        : "r"((a)[0]), "r"((a)[1]), "r"((a)[2]), "r"((a)[3]),                 \
          "r"((b)[0]), "r"((b)[1]))

#define LDSM4(r0, r1, r2, r3, addr)                                           \
    asm volatile("ldmatrix.sync.aligned.m8n8.x4.shared.b16 {%0,%1,%2,%3},[%4];" \
                 : "=r"(r0), "=r"(r1), "=r"(r2), "=r"(r3) : "r"(addr))

#define CPASYNC16(s, g)                                                       \
    asm volatile("cp.async.cg.shared.global [%0], [%1], 16;" :: "r"(s), "l"(g))
#define CPCOMMIT() asm volatile("cp.async.commit_group;")
#define CPWAIT1()  asm volatile("cp.async.wait_group 1;")
#define CPWAIT0()  asm volatile("cp.async.wait_group 0;")

// ---------------------------------------------------------------------------
// 3xBF16 split GEMM (standalone, fp32 C epilogue). C = A @ B^T.
// BM=64, BN template (64/128), BK=32, 256 threads. grid = (N/BN, M/64).
// ---------------------------------------------------------------------------
template <int BN>
__global__ void __launch_bounds__(256) gemmA(
    const __nv_bfloat16* __restrict__ Ah, const __nv_bfloat16* __restrict__ Al,
    const __nv_bfloat16* __restrict__ Bh, const __nv_bfloat16* __restrict__ Bl,
    float* __restrict__ C, int K, int N)
{
    constexpr int NI = BN / 32;
    constexpr int STG = 5120 + 2 * BN * 40;

    extern __shared__ __nv_bfloat16 smem[];
    const uint32_t sb0 = smem_u32(smem);

    const int tid = threadIdx.x;
    const int lane = tid & 31;
    const int wid = tid >> 5;
    const int wm = wid >> 2;
    const int wn = wid & 3;
    const int g = lane >> 2;
    const int ti = lane & 3;

    const int bm = blockIdx.y * 64;
    const int bn = blockIdx.x * BN;

    const int arow = tid >> 2;
    const int akq = tid & 3;

    const int i1 = (lane >> 3) & 1, i2 = lane >> 4, l7 = lane & 7;
    const uint32_t aoff = ((wm * 32 + i1 * 8 + l7) * 40 + i2 * 8) * 2;
    const uint32_t boff = (5120 + (wn * (BN / 4) + i2 * 8 + l7) * 40 + i1 * 8) * 2;

    float acc[2][NI][4];
#pragma unroll
    for (int i = 0; i < 2; i++)
#pragma unroll
        for (int j = 0; j < NI; j++)
#pragma unroll
            for (int v = 0; v < 4; v++) acc[i][j][v] = 0.f;

    const int nk = K >> 5;

    auto load_stage = [&](int stage, int k0) {
        const uint32_t sb = sb0 + stage * STG * 2;
        {
            const uint32_t so = sb + (arow * 40 + akq * 8) * 2;
            CPASYNC16(so, Ah + (size_t)(bm + arow) * K + k0 + akq * 8);
            CPASYNC16(so + 2560 * 2, Al + (size_t)(bm + arow) * K + k0 + akq * 8);
        }
#pragma unroll
        for (int rep = 0; rep < BN / 64; rep++) {
            const int idx = tid + rep * 256;
            const int brow = idx >> 2;
            const int bkq = idx & 3;
            const uint32_t so = sb + (5120 + brow * 40 + bkq * 8) * 2;
            CPASYNC16(so, Bh + (size_t)(bn + brow) * K + k0 + bkq * 8);
            CPASYNC16(so + BN * 40 * 2, Bl + (size_t)(bn + brow) * K + k0 + bkq * 8);
        }
        CPCOMMIT();
    };

    load_stage(0, 0);

    for (int kt = 0; kt < nk; kt++) {
        if (kt + 1 < nk) { load_stage((kt + 1) & 1, (kt + 1) * 32); CPWAIT1(); }
        else             { CPWAIT0(); }
        __syncthreads();

        const uint32_t sb = sb0 + (kt & 1) * STG * 2;
#pragma unroll
        for (int q = 0; q < 2; q++) {
            uint32_t ah[2][4], al[2][4], bh[NI][2], bl[NI][2];
            const uint32_t ka = sb + aoff + q * 32;
            LDSM4(ah[0][0], ah[0][1], ah[0][2], ah[0][3], ka);
            LDSM4(ah[1][0], ah[1][1], ah[1][2], ah[1][3], ka + 1280);
            LDSM4(al[0][0], al[0][1], al[0][2], al[0][3], ka + 5120);
            LDSM4(al[1][0], al[1][1], al[1][2], al[1][3], ka + 5120 + 1280);
            const uint32_t kb = sb + boff + q * 32;
#pragma unroll
            for (int p = 0; p < NI / 2; p++) {
                LDSM4(bh[2 * p][0], bh[2 * p][1], bh[2 * p + 1][0], bh[2 * p + 1][1],
                      kb + p * 1280);
                LDSM4(bl[2 * p][0], bl[2 * p][1], bl[2 * p + 1][0], bl[2 * p + 1][1],
                      kb + BN * 80 + p * 1280);
            }
#pragma unroll
            for (int mi = 0; mi < 2; mi++)
#pragma unroll
                for (int ni = 0; ni < NI; ni++) {
                    MMA_BF16(acc[mi][ni], ah[mi], bh[ni]);
                    MMA_BF16(acc[mi][ni], ah[mi], bl[ni]);
                    MMA_BF16(acc[mi][ni], al[mi], bh[ni]);
                }
        }
        __syncthreads();
    }

#pragma unroll
    for (int mi = 0; mi < 2; mi++) {
        const int row = bm + wm * 32 + mi * 16 + g;
#pragma unroll
        for (int ni = 0; ni < NI; ni++) {
            const int col = bn + wn * (BN / 4) + ni * 8 + 2 * ti;
            *(float2*)(C + (size_t)row * N + col) =
                make_float2(acc[mi][ni][0], acc[mi][ni][1]);
            *(float2*)(C + (size_t)(row + 8) * N + col) =
                make_float2(acc[mi][ni][2], acc[mi][ni][3]);
        }
    }
}

#define SMEM_B128 (2 * (5120 + 2 * 128 * 40) * 2)   // 61440
#define SMEM_B64  (2 * (5120 + 2 * 64 * 40) * 2)    // 40960

// ---------------------------------------------------------------------------
// FUSED per-step encoder kernel (R10 structure, 256 threads) with BK=64.
// Phase 1 stage layout (bytes, stride-72 rows = 144 B):
//   A_hi@0 (9216)  A_lo@9216 (9216)  B_hi@18432 (18432)  B_lo@36864 (18432)
//   stage = 55296 B, 2 stages = 110592 B.
// Phase 2: unchanged from R10 (AC_hi@0, AC_lo@17408 B elems offset 17408
//   elements, Wc double-buffer) — reuses the first 75776 B.
// grid = (16 n-tiles, 8 batches) = 128 CTAs.
// ---------------------------------------------------------------------------
#define STG1B 55296
#define SMEM_STEP 110592

__global__ void __launch_bounds__(256) k_step()
{
    extern __shared__ __nv_bfloat16 smem[];
    const uint32_t sb0 = smem_u32(smem);

    const int tid = threadIdx.x;
    const int lane = tid & 31;
    const int wid = tid >> 5;
    const int wm = wid >> 2;
    const int wn = wid & 3;
    const int g = lane >> 2;
    const int ti = lane & 3;
    const int bm = blockIdx.x * 64;       // n-tile base
    const int b = blockIdx.y;             // batch

    const __nv_bfloat16* BH = g_hidTH + (size_t)b * 128 * 1024;
    const __nv_bfloat16* BL = g_hidTL + (size_t)b * 128 * 1024;

    const int i1 = (lane >> 3) & 1, i2 = lane >> 4, l7 = lane & 7;
    // phase-1 byte offsets (stride-72-element rows)
    const uint32_t aoff = ((wm * 32 + i1 * 8 + l7) * 72 + i2 * 8) * 2;
    const uint32_t boff = 18432 + ((wn * 32 + i2 * 8 + l7) * 72 + i1 * 8) * 2;
    // phase-2 (AC stride-136, Wc stride-40; unchanged from R10)
    const uint32_t aoff2 = ((wm * 32 + i1 * 8 + l7) * 136 + i2 * 8) * 2;
    const uint32_t boff2 = ((wn * 32 + i2 * 8 + l7) * 40 + i1 * 8) * 2;

    float acc[2][4][4];
#pragma unroll
    for (int i = 0; i < 2; i++)
#pragma unroll
        for (int j = 0; j < 4; j++)
#pragma unroll
            for (int v = 0; v < 4; v++) acc[i][j][v] = 0.f;

    // ---------------- phase 1: AC = adj_tile @ hidT_b^T (BK=64) ----------------
    auto load_stage = [&](int stage, int k0) {
        const uint32_t sb = sb0 + stage * STG1B;
        // A: 64 rows x 64k hi+lo   (A_lo = A_hi + 9216 B)
#pragma unroll
        for (int rep = 0; rep < 2; rep++) {
            const int idx = tid + rep * 256;
            const int row = idx >> 3, ch = idx & 7;
            const uint32_t so = sb + (row * 72 + ch * 8) * 2;
            CPASYNC16(so, g_adjH + (size_t)(bm + row) * 1024 + k0 + ch * 8);
            CPASYNC16(so + 9216, g_adjL + (size_t)(bm + row) * 1024 + k0 + ch * 8);
        }
        // B: 128 rows x 64k hi+lo  (B_lo = B_hi + 18432 B)
#pragma unroll
        for (int rep = 0; rep < 4; rep++) {
            const int idx = tid + rep * 256;
            const int row = idx >> 3, ch = idx & 7;
            const uint32_t so = sb + 18432 + (row * 72 + ch * 8) * 2;
            CPASYNC16(so, BH + (size_t)row * 1024 + k0 + ch * 8);
            CPASYNC16(so + 18432, BL + (size_t)row * 1024 + k0 + ch * 8);
        }
        CPCOMMIT();
    };

    load_stage(0, 0);

    for (int kt = 0; kt < 16; kt++) {
        if (kt + 1 < 16) { load_stage((kt + 1) & 1, (kt + 1) * 64); CPWAIT1(); }
        else             { CPWAIT0(); }
        __syncthreads();

        const uint32_t sb = sb0 + (kt & 1) * STG1B;
#pragma unroll
        for (int q = 0; q < 4; q++) {
            uint32_t ah[2][4], al[2][4], bh[4][2], bl[4][2];
            const uint32_t ka = sb + aoff + q * 32;
            LDSM4(ah[0][0], ah[0][1], ah[0][2], ah[0][3], ka);
            LDSM4(ah[1][0], ah[1][1], ah[1][2], ah[1][3], ka + 2304);
            LDSM4(al[0][0], al[0][1], al[0][2], al[0][3], ka + 9216);
            LDSM4(al[1][0], al[1][1], al[1][2], al[1][3], ka + 9216 + 2304);
            const uint32_t kb = sb + boff + q * 32;
#pragma unroll
            for (int p = 0; p < 2; p++) {
                LDSM4(bh[2 * p][0], bh[2 * p][1], bh[2 * p + 1][0], bh[2 * p + 1][1],
                      kb + p * 2304);
                LDSM4(bl[2 * p][0], bl[2 * p][1], bl[2 * p + 1][0], bl[2 * p + 1][1],
                      kb + 18432 + p * 2304);
            }
#pragma unroll
            for (int mi = 0; mi < 2; mi++)
#pragma unroll
                for (int ni = 0; ni < 4; ni++) {
                    MMA_BF16(acc[mi][ni], ah[mi], bh[ni]);
                    MMA_BF16(acc[mi][ni], ah[mi], bl[ni]);
                    MMA_BF16(acc[mi][ni], al[mi], bh[ni]);
                }
        }
        __syncthreads();
    }

    // ---- AC -> SMEM (split hi/lo), rows stride 136 (unchanged) ----
#pragma unroll
    for (int mi = 0; mi < 2; mi++) {
        const int row = wm * 32 + mi * 16 + g;
#pragma unroll
        for (int ni = 0; ni < 4; ni++) {
            const int col = wn * 32 + ni * 8 + 2 * ti;
            const uint32_t o0 = (uint32_t)(row * 136 + col) * 2;
            const uint32_t o1 = (uint32_t)((row + 8) * 136 + col) * 2;
            asm volatile("st.shared.b32 [%0], %1;" :: "r"(sb0 + o0),
                         "r"(pack2(acc[mi][ni][0], acc[mi][ni][1])));
            asm volatile("st.shared.b32 [%0], %1;" :: "r"(sb0 + 17408 + o0),
                         "r"(pack2lo(acc[mi][ni][0], acc[mi][ni][1])));
            asm volatile("st.shared.b32 [%0], %1;" :: "r"(sb0 + o1),
                         "r"(pack2(acc[mi][ni][2], acc[mi][ni][3])));
            asm volatile("st.shared.b32 [%0], %1;" :: "r"(sb0 + 17408 + o1),
                         "r"(pack2lo(acc[mi][ni][2], acc[mi][ni][3])));
        }
    }
    __syncthreads();

    // ---------------- phase 2: G = AC @ Wc^T (K=128) (unchanged from R10) ------
    auto loadWc = [&](int idx, int st) {
        const uint32_t base = sb0 + (17408 + st * 10240) * 2;
        const int nc2 = idx >> 2, kc2 = idx & 3;
#pragma unroll
        for (int rep = 0; rep < 2; rep++) {
            const int e = tid + rep * 256;
            const int row = e >> 2, q4 = e & 3;
            const uint32_t dst = base + (row * 40 + q4 * 8) * 2;
            CPASYNC16(dst, g_wcH + (nc2 * 128 + row) * 128 + kc2 * 32 + q4 * 8);
            CPASYNC16(dst + 5120 * 2, g_wcL + (nc2 * 128 + row) * 128 + kc2 * 32 + q4 * 8);
        }
        CPCOMMIT();
    };

    loadWc(0, 0);

    for (int nc = 0; nc < 4; nc++) {
#pragma unroll
        for (int i = 0; i < 2; i++)
#pragma unroll
            for (int j = 0; j < 4; j++)
#pragma unroll
                for (int v = 0; v < 4; v++) acc[i][j][v] = 0.f;

        for (int kc = 0; kc < 4; kc++) {
            const int gi = nc * 4 + kc;
            if (gi < 15) { loadWc(gi + 1, (gi + 1) & 1); CPWAIT1(); }
            else         { CPWAIT0(); }
            __syncthreads();
            const uint32_t wcb = sb0 + (17408 + (gi & 1) * 10240) * 2;
#pragma unroll
            for (int q = 0; q < 2; q++) {
                uint32_t ah[2][4], al[2][4], bh[4][2], bl[4][2];
                const uint32_t ka = sb0 + aoff2 + (kc * 32 + q * 16) * 2;
                LDSM4(ah[0][0], ah[0][1], ah[0][2], ah[0][3], ka);
                LDSM4(ah[1][0], ah[1][1], ah[1][2], ah[1][3], ka + 4352);
                LDSM4(al[0][0], al[0][1], al[0][2], al[0][3], ka + 17408);
                LDSM4(al[1][0], al[1][1], al[1][2], al[1][3], ka + 17408 + 4352);
                const uint32_t kb = wcb + boff2 + q * 32;
#pragma unroll
                for (int p = 0; p < 2; p++) {
                    LDSM4(bh[2 * p][0], bh[2 * p][1], bh[2 * p + 1][0], bh[2 * p + 1][1],
                          kb + p * 1280);
                    LDSM4(bl[2 * p][0], bl[2 * p][1], bl[2 * p + 1][0], bl[2 * p + 1][1],
                          kb + 10240 + p * 1280);
                }
#pragma unroll
                for (int mi = 0; mi < 2; mi++)
#pragma unroll
                    for (int ni = 0; ni < 4; ni++) {
                        MMA_BF16(acc[mi][ni], ah[mi], bh[ni]);
                        MMA_BF16(acc[mi][ni], ah[mi], bl[ni]);
                        MMA_BF16(acc[mi][ni], al[mi], bh[ni]);
                    }
            }
            __syncthreads();
        }

        // write G chunk (node-major rows r = n*8+b)
#pragma unroll
        for (int mi = 0; mi < 2; mi++) {
            const int n0 = bm + wm * 32 + mi * 16 + g;
#pragma unroll
            for (int ni = 0; ni < 4; ni++) {
                const int col = nc * 128 + wn * 32 + ni * 8 + 2 * ti;
                *(float2*)(g_G + ((size_t)n0 * 8 + b) * 512 + col) =
                    make_float2(acc[mi][ni][0], acc[mi][ni][1]);
                *(float2*)(g_G + ((size_t)(n0 + 8) * 8 + b) * 512 + col) =
                    make_float2(acc[mi][ni][2], acc[mi][ni][3]);
            }
        }
    }
}

// ---------------------------------------------------------------------------
// Persistent fused decoder: 32 LSTM steps in ONE launch (proven).
// grid 128 CTAs x 512 threads. Writes the (b,n,h)-permuted output directly.
// ---------------------------------------------------------------------------
#define DEC_AH 0
#define DEC_AL 8704
#define DEC_B0 17408
#define DEC_STG 40960
#define DEC_ELEMS (DEC_B0 + 2 * DEC_STG)
#define DEC_SMEM (DEC_ELEMS * 2)

__global__ void __launch_bounds__(512) k_dec(const float* __restrict__ Gc,
                                             const float* __restrict__ bih,
                                             const float* __restrict__ bhh,
                                             float* __restrict__ out)
{
    extern __shared__ __nv_bfloat16 sm[];
    __shared__ float sbias[512];
    const uint32_t sb = smem_u32(sm);

    const int tid = threadIdx.x;
    const int lane = tid & 31;
    const int wid = tid >> 5;
    const int wm = wid >> 3;
    const int wn = wid & 7;
    const int g = lane >> 2;
    const int ti = lane & 3;
    const int bm = blockIdx.x * 64;

    if (tid < 512) sbias[tid] = bih[tid] + bhh[tid];
    for (int i = tid; i < 8704; i += 512) { sm[DEC_AH + i] = __float2bfloat16(0.f);
                                            sm[DEC_AL + i] = __float2bfloat16(0.f); }

    float cxr[16];
#pragma unroll
    for (int i = 0; i < 16; i++) cxr[i] = 0.f;

    float acc[2][8][4];
#pragma unroll
    for (int mi = 0; mi < 2; mi++)
#pragma unroll
        for (int j = 0; j < 8; j++)
#pragma unroll
            for (int v = 0; v < 4; v++) acc[mi][j][v] = 0.f;

    auto loadB = [&](int kc, int st) {
        const uint32_t base = sb + (DEC_B0 + st * DEC_STG) * 2;
#pragma unroll
        for (int rep = 0; rep < 4; rep++) {
            const int idx = tid + rep * 512;
            const int row = idx >> 2;
            const int qq = idx & 3;
            const uint32_t dst = base + (row * 40 + qq * 8) * 2;
            CPASYNC16(dst, g_whhH + row * 128 + kc * 32 + qq * 8);
            CPASYNC16(dst + 20480 * 2, g_whhL + row * 128 + kc * 32 + qq * 8);
        }
        CPCOMMIT();
    };

    const int i1 = (lane >> 3) & 1, i2 = lane >> 4, l7 = lane & 7;
    const uint32_t aoff = ((wm * 32 + i1 * 8 + l7) * 136 + i2 * 8) * 2;
    const uint32_t boffrel = ((wn * 16 + i2 * 8 + l7) * 40 + i1 * 8) * 2;

    loadB(0, 0);

    for (int step = 0; step < Ss; step++) {
        for (int kc = 0; kc < 4; kc++) {
            const int gi = step * 4 + kc;
            loadB((gi + 1) & 3, (gi + 1) & 1);
            CPWAIT1();
            __syncthreads();
            const uint32_t bbase = sb + (DEC_B0 + (gi & 1) * DEC_STG) * 2;
#pragma unroll
            for (int q = 0; q < 2; q++) {
                uint32_t ah[2][4], al[2][4];
                const uint32_t ka = sb + aoff + (kc * 32 + q * 16) * 2;
                LDSM4(ah[0][0], ah[0][1], ah[0][2], ah[0][3], ka);
                LDSM4(ah[1][0], ah[1][1], ah[1][2], ah[1][3], ka + 4352);
                LDSM4(al[0][0], al[0][1], al[0][2], al[0][3], ka + 17408);
                LDSM4(al[1][0], al[1][1], al[1][2], al[1][3], ka + 17408 + 4352);
#pragma unroll
                for (int pp = 0; pp < 4; pp++) {
                    uint32_t bh[2][2], bl[2][2];
                    const uint32_t kb = bbase + boffrel + q * 32 + pp * 10240;
                    LDSM4(bh[0][0], bh[0][1], bh[1][0], bh[1][1], kb);
                    LDSM4(bl[0][0], bl[0][1], bl[1][0], bl[1][1], kb + 40960);
#pragma unroll
                    for (int mi = 0; mi < 2; mi++)
#pragma unroll
                        for (int jj = 0; jj < 2; jj++) {
                            float* a = acc[mi][pp * 2 + jj];
                            MMA_BF16(a, ah[mi], bh[jj]);
                            MMA_BF16(a, ah[mi], bl[jj]);
                            MMA_BF16(a, al[mi], bh[jj]);
                        }
                }
            }
            __syncthreads();
        }
        const int last = (step == Ss - 1);
#pragma unroll
        for (int mi = 0; mi < 2; mi++)
#pragma unroll
            for (int rh = 0; rh < 2; rh++)
#pragma unroll
                for (int sub = 0; sub < 2; sub++)
#pragma unroll
                    for (int p = 0; p < 2; p++) {
                        const int rowLoc = wm * 32 + mi * 16 + rh * 8 + g;
                        const int h = wn * 16 + sub * 8 + 2 * ti + p;
                        const int grow = bm + rowLoc;
                        const int ci = mi * 8 + rh * 4 + sub * 2 + p;
                        float ig = acc[mi][0 + sub][rh * 2 + p] + Gc[(size_t)grow * 512 + h] + sbias[h];
                        float fg = acc[mi][2 + sub][rh * 2 + p] + Gc[(size_t)grow * 512 + 128 + h] + sbias[128 + h];
                        float gt = acc[mi][4 + sub][rh * 2 + p] + Gc[(size_t)grow * 512 + 256 + h] + sbias[256 + h];
                        float og = acc[mi][6 + sub][rh * 2 + p] + Gc[(size_t)grow * 512 + 384 + h] + sbias[384 + h];
                        ig = fsigm(ig); fg = fsigm(fg); gt = ftanh(gt); og = fsigm(og);
                        const float cx = fg * cxr[ci] + ig * gt;
                        cxr[ci] = cx;
                        const float hxv = og * ftanh(cx);
                        __nv_bfloat16 hh, ll;
                        splitHL(hxv, hh, ll);
                        sm[DEC_AH + rowLoc * 136 + h] = hh;
                        sm[DEC_AL + rowLoc * 136 + h] = ll;
                        if (last) {
                            const int bq = grow & 7, n = grow >> 3;
                            out[((size_t)bq * 1024 + n) * 128 + h] = hxv;
                        }
                        acc[mi][0 + sub][rh * 2 + p] = 0.f;
                        acc[mi][2 + sub][rh * 2 + p] = 0.f;
                        acc[mi][4 + sub][rh * 2 + p] = 0.f;
                        acc[mi][6 + sub][rh * 2 + p] = 0.f;
                    }
        __syncthreads();
    }
}

// ---------------------------------------------------------------------------
// Converters & small kernels
// ---------------------------------------------------------------------------
__global__ void c_splitHL(const float* __restrict__ src,
                          __nv_bfloat16* __restrict__ dH, __nv_bfloat16* __restrict__ dL,
                          int Kc, int Kp)
{
    const int row = blockIdx.y;
    const int k = blockIdx.x * 256 + threadIdx.x;
    if (k >= Kp) return;
    const float v = (k < Kc) ? src[(size_t)row * Kc + k] : 0.f;
    __nv_bfloat16 h, l;
    splitHL(v, h, l);
    dH[(size_t)row * Kp + k] = h;
    dL[(size_t)row * Kp + k] = l;
}

__global__ void c_split_x(const float* __restrict__ x)
{
    const int j = blockIdx.y;
    const int k = blockIdx.x * 256 + threadIdx.x;
    const int s = j >> 5, b = (j >> 2) & 7, f = j & 3;
    const float v = x[((size_t)(b * Ss + s) * Nn + k) * 4 + f];
    __nv_bfloat16 h, l;
    splitHL(v, h, l);
    g_xTH[(size_t)j * 1024 + k] = h;
    g_xTL[(size_t)j * 1024 + k] = l;
}

__global__ void c_wprep(const float* __restrict__ W1, const float* __restrict__ W2)
{
    const int idx = blockIdx.x * 256 + threadIdx.x;
    if (idx < 512 * 128) {
        const int gate = idx >> 7, k = idx & 127;
        const int c = k + 4;
        const float v = (gate < G3) ? W1[c * G3 + gate] : W2[c * Hh + (gate - G3)];
        __nv_bfloat16 h, l;
        splitHL(v, h, l);
        g_wcH[idx] = h;
        g_wcL[idx] = l;
    }
    if (idx < 4 * 512) {
        const int k = idx >> 9, c = idx & 511;
        g_W4[idx] = (c < G3) ? W1[k * G3 + c] : W2[k * Hh + (c - G3)];
    }
}

__global__ void k_zero()
{
    const int idx = blockIdx.x * blockDim.x + threadIdx.x;   // 1M threads
    *(float4*)(g_G + (size_t)idx * 4) = make_float4(0.f, 0.f, 0.f, 0.f);
    g_csum[idx] = 0.f;
}

// Encoder elementwise: flat-chunk gate indexing + AX rank-4 correction,
// fused transposed hi/lo split; on last step also writes split csum.
__global__ void k_enc_elem(const float* __restrict__ b1, const float* __restrict__ b2,
                           int s, int last)
{
    __shared__ float t[32][33];
    const int b = blockIdx.x >> 7;
    const int nt = (blockIdx.x >> 2) & 31;
    const int ht = blockIdx.x & 3;
    const int n0 = nt * 32, h0 = ht * 32;
    const int hl = threadIdx.x & 31;
    const int w8 = threadIdx.x >> 5;

#pragma unroll
    for (int q = 0; q < 4; q++) {
        const int nl = w8 + q * 8;
        const int n = n0 + nl;
        const int h = h0 + hl;
        const int j = n * 128 + h;
        const int ji = j + NHf;
        const int ni = ji / G3, ci = ji - ni * G3;
        const int jo = j + 2 * NHf;
        const int no = jo / G3, co = jo - no * G3;
        const int sb4 = s * 32 + b * 4;

        float igp = g_G[(size_t)(ni * 8 + b) * 512 + ci] + b1[ci];
        float ogp = g_G[(size_t)(no * 8 + b) * 512 + co] + b1[co];
        float csp = g_G[(size_t)(n * 8 + b) * 512 + G3 + h] + b2[h];
#pragma unroll
        for (int k = 0; k < 4; k++) {
            igp += g_AX[(size_t)ni * 1024 + sb4 + k] * g_W4[k * 512 + ci];
            ogp += g_AX[(size_t)no * 1024 + sb4 + k] * g_W4[k * 512 + co];
            csp += g_AX[(size_t)n * 1024 + sb4 + k] * g_W4[k * 512 + G3 + h];
        }
        const float hn = fsigm(ogp) * ftanh(fsigm(igp) * ftanh(csp));
        const size_t co2 = (size_t)(n * 8 + b) * 128 + h;
        const float cs2 = g_csum[co2] + hn;
        g_csum[co2] = cs2;
        if (last) {
            __nv_bfloat16 ch, cl;
            splitHL(cs2, ch, cl);
            g_csH[co2] = ch;
            g_csL[co2] = cl;
        }
        t[hl][nl] = hn;
    }
    __syncthreads();
#pragma unroll
    for (int q = 0; q < 4; q++) {
        const int h2 = w8 + q * 8;
        const float v = t[h2][hl];
        __nv_bfloat16 hh, ll;
        splitHL(v, hh, ll);
        g_hidTH[(size_t)(b * 128 + h0 + h2) * 1024 + n0 + hl] = hh;
        g_hidTL[(size_t)(b * 128 + h0 + h2) * 1024 + n0 + hl] = ll;
    }
}

// ---------------------------------------------------------------------------
// Launch (single stream)
// ---------------------------------------------------------------------------
extern "C" void kernel_launch(void* const* d_in, const int* in_sizes, int n_in,
                              void* d_out, int out_size)
{
    (void)in_sizes; (void)n_in; (void)out_size;
    const float* x   = (const float*)d_in[0];
    const float* adj = (const float*)d_in[1];
    const float* W1  = (const float*)d_in[2];
    const float* b1  = (const float*)d_in[3];
    const float* W2  = (const float*)d_in[4];
    const float* b2  = (const float*)d_in[5];
    const float* Wih = (const float*)d_in[6];
    const float* Whh = (const float*)d_in[7];
    const float* bih = (const float*)d_in[8];
    const float* bhh = (const float*)d_in[9];
    float* out = (float*)d_out;

    cudaFuncSetAttribute(gemmA<128>, cudaFuncAttributeMaxDynamicSharedMemorySize, SMEM_B128);
    cudaFuncSetAttribute(gemmA<64>, cudaFuncAttributeMaxDynamicSharedMemorySize, SMEM_B64);
    cudaFuncSetAttribute(k_step, cudaFuncAttributeMaxDynamicSharedMemorySize, SMEM_STEP);
    cudaFuncSetAttribute(k_dec, cudaFuncAttributeMaxDynamicSharedMemorySize, DEC_SMEM);

    __nv_bfloat16 *pAdjH, *pAdjL, *pXH, *pXL, *pWiH, *pWiL, *pWhH, *pWhL, *pCsH, *pCsL;
    float *pAX, *pGc;
    cudaGetSymbolAddress((void**)&pAdjH, g_adjH);
    cudaGetSymbolAddress((void**)&pAdjL, g_adjL);
    cudaGetSymbolAddress((void**)&pXH, g_xTH);
    cudaGetSymbolAddress((void**)&pXL, g_xTL);
    cudaGetSymbolAddress((void**)&pWiH, g_wihH);
    cudaGetSymbolAddress((void**)&pWiL, g_wihL);
    cudaGetSymbolAddress((void**)&pWhH, g_whhH);
    cudaGetSymbolAddress((void**)&pWhL, g_whhL);
    cudaGetSymbolAddress((void**)&pCsH, g_csH);
    cudaGetSymbolAddress((void**)&pCsL, g_csL);
    cudaGetSymbolAddress((void**)&pAX, g_AX);
    cudaGetSymbolAddress((void**)&pGc, g_Gc);

    k_zero<<<4096, 256>>>();
    c_wprep<<<256, 256>>>(W1, W2);
    c_splitHL<<<dim3(4, 1024), 256>>>(adj, pAdjH, pAdjL, 1024, 1024);
    c_split_x<<<dim3(4, 1024), 256>>>(x);
    c_splitHL<<<dim3(1, 512), 256>>>(Wih, pWiH, pWiL, 128, 128);
    c_splitHL<<<dim3(1, 512), 256>>>(Whh, pWhH, pWhL, 128, 128);

    // AX = adj @ x^T (all steps)
    gemmA<64><<<dim3(16, 16), 256, SMEM_B64>>>(pAdjH, pAdjL, pXH, pXL, pAX, 1024, 1024);

    // ---------------- Encoder: 32 recurrent steps (2 kernels each) --------
    for (int s = 0; s < Ss; s++) {
        if (s) k_step<<<dim3(16, 8), 256, SMEM_STEP>>>();
        k_enc_elem<<<1024, 256>>>(b1, b2, s, s == Ss - 1);
    }

    // ---------------- Decoder ----------------
    gemmA<128><<<dim3(4, 128), 256, SMEM_B128>>>(pCsH, pCsL, pWiH, pWiL, pGc, 128, 512);
    k_dec<<<128, 512, DEC_SMEM>>>(pGc, bih, bhh, out);
}

// round 16
// speedup vs baseline: 1.1355x; 1.0420x over previous
#include <cuda_runtime.h>
#include <cuda_bf16.h>
#include <stdint.h>

// ---------------------------------------------------------------------------
// Problem constants
// ---------------------------------------------------------------------------
#define Bb 8
#define Ss 32
#define Nn 1024
#define Hh 128
#define NBROWS 8192
#define NBH 1048576
#define NHf 131072
#define G3 384

// ---------------------------------------------------------------------------
// Scratch (device globals; no allocation allowed). Node-major rows r = n*8+b.
// ---------------------------------------------------------------------------
__device__ __align__(16) __nv_bfloat16 g_adjH[1024 * 1024], g_adjL[1024 * 1024];
__device__ __align__(16) __nv_bfloat16 g_xTH[1024 * 1024], g_xTL[1024 * 1024];
__device__ __align__(16) __nv_bfloat16 g_hidTH[1024 * 1024], g_hidTL[1024 * 1024];
__device__ __align__(16) __nv_bfloat16 g_wcH[512 * 128], g_wcL[512 * 128];
__device__ __align__(16) __nv_bfloat16 g_wihH[512 * 128], g_wihL[512 * 128];
__device__ __align__(16) __nv_bfloat16 g_whhH[512 * 128], g_whhL[512 * 128];
__device__ __align__(16) __nv_bfloat16 g_csH[8192 * 128], g_csL[8192 * 128];

__device__ float g_W4[4 * 512];          // Wc rows 0..3, layout [k][gate]
__device__ float g_AX[1024 * 1024];
__device__ float g_G[NBROWS * 512];
__device__ float g_Gc[NBROWS * 512];
__device__ float g_csum[NBH];

// ---------------------------------------------------------------------------
// Helpers
// ---------------------------------------------------------------------------
__device__ __forceinline__ float fsigm(float x) {
    return __fdividef(1.f, 1.f + __expf(-x));
}
__device__ __forceinline__ float ftanh(float x) {
    return 1.f - __fdividef(2.f, __expf(2.f * x) + 1.f);
}

__device__ __forceinline__ uint32_t smem_u32(const void* p) {
    uint32_t a;
    asm("{ .reg .u64 t; cvta.to.shared.u64 t, %1; cvt.u32.u64 %0, t; }" : "=r"(a) : "l"(p));
    return a;
}

__device__ __forceinline__ void splitHL(float v, __nv_bfloat16& h, __nv_bfloat16& l) {
    h = __float2bfloat16(v);
    l = __float2bfloat16(v - __bfloat162float(h));
}
__device__ __forceinline__ uint32_t pack2(float v0, float v1) {
    __nv_bfloat16 a = __float2bfloat16(v0), b = __float2bfloat16(v1);
    return (uint32_t)*(unsigned short*)&a | ((uint32_t)*(unsigned short*)&b << 16);
}
__device__ __forceinline__ uint32_t pack2lo(float v0, float v1) {
    __nv_bfloat16 a = __float2bfloat16(v0);
    __nv_bfloat16 b = __float2bfloat16(v1);
    float l0 = v0 - __bfloat162float(a), l1 = v1 - __bfloat162float(b);
    __nv_bfloat16 c = __float2bfloat16(l0), d = __float2bfloat16(l1);
    return (uint32_t)*(unsigned short*)&c | ((uint32_t)*(unsigned short*)&d << 16);
}

#define MMA_BF16(c, a, b)                                                     \
    asm volatile(                                                             \
        "mma.sync.aligned.m16n8k16.row.col.f32.bf16.bf16.f32 "                \
        "{%0,%1,%2,%3},{%4,%5,%6,%7},{%8,%9},{%0,%1,%2,%3};"                  \
        : "+f"((c)[0]), "+f"((c)[1]), "+f"((c)[2]), "+f"((c)[3])              \
        : "r"((a)[0]), "r"((a)[1]), "r"((a)[2]), "r"((a)[3]),                 \
          "r"((b)[0]), "r"((b)[1]))

#define LDSM4(r0, r1, r2, r3, addr)                                           \
    asm volatile("ldmatrix.sync.aligned.m8n8.x4.shared.b16 {%0,%1,%2,%3},[%4];" \
                 : "=r"(r0), "=r"(r1), "=r"(r2), "=r"(r3) : "r"(addr))

#define CPASYNC16(s, g)                                                       \
    asm volatile("cp.async.cg.shared.global [%0], [%1], 16;" :: "r"(s), "l"(g))
#define CPCOMMIT() asm volatile("cp.async.commit_group;")
#define CPWAIT1()  asm volatile("cp.async.wait_group 1;")
#define CPWAIT0()  asm volatile("cp.async.wait_group 0;")

// ---------------------------------------------------------------------------
// 3xBF16 split GEMM (standalone, fp32 C epilogue). C = A @ B^T.
// BM=64, BN template (64/128), BK=32, 256 threads. grid = (N/BN, M/64).
// ---------------------------------------------------------------------------
template <int BN>
__global__ void __launch_bounds__(256) gemmA(
    const __nv_bfloat16* __restrict__ Ah, const __nv_bfloat16* __restrict__ Al,
    const __nv_bfloat16* __restrict__ Bh, const __nv_bfloat16* __restrict__ Bl,
    float* __restrict__ C, int K, int N)
{
    constexpr int NI = BN / 32;
    constexpr int STG = 5120 + 2 * BN * 40;

    extern __shared__ __nv_bfloat16 smem[];
    const uint32_t sb0 = smem_u32(smem);

    const int tid = threadIdx.x;
    const int lane = tid & 31;
    const int wid = tid >> 5;
    const int wm = wid >> 2;
    const int wn = wid & 3;
    const int g = lane >> 2;
    const int ti = lane & 3;

    const int bm = blockIdx.y * 64;
    const int bn = blockIdx.x * BN;

    const int arow = tid >> 2;
    const int akq = tid & 3;

    const int i1 = (lane >> 3) & 1, i2 = lane >> 4, l7 = lane & 7;
    const uint32_t aoff = ((wm * 32 + i1 * 8 + l7) * 40 + i2 * 8) * 2;
    const uint32_t boff = (5120 + (wn * (BN / 4) + i2 * 8 + l7) * 40 + i1 * 8) * 2;

    float acc[2][NI][4];
#pragma unroll
    for (int i = 0; i < 2; i++)
#pragma unroll
        for (int j = 0; j < NI; j++)
#pragma unroll
            for (int v = 0; v < 4; v++) acc[i][j][v] = 0.f;

    const int nk = K >> 5;

    auto load_stage = [&](int stage, int k0) {
        const uint32_t sb = sb0 + stage * STG * 2;
        {
            const uint32_t so = sb + (arow * 40 + akq * 8) * 2;
            CPASYNC16(so, Ah + (size_t)(bm + arow) * K + k0 + akq * 8);
            CPASYNC16(so + 2560 * 2, Al + (size_t)(bm + arow) * K + k0 + akq * 8);
        }
#pragma unroll
        for (int rep = 0; rep < BN / 64; rep++) {
            const int idx = tid + rep * 256;
            const int brow = idx >> 2;
            const int bkq = idx & 3;
            const uint32_t so = sb + (5120 + brow * 40 + bkq * 8) * 2;
            CPASYNC16(so, Bh + (size_t)(bn + brow) * K + k0 + bkq * 8);
            CPASYNC16(so + BN * 40 * 2, Bl + (size_t)(bn + brow) * K + k0 + bkq * 8);
        }
        CPCOMMIT();
    };

    load_stage(0, 0);

    for (int kt = 0; kt < nk; kt++) {
        if (kt + 1 < nk) { load_stage((kt + 1) & 1, (kt + 1) * 32); CPWAIT1(); }
        else             { CPWAIT0(); }
        __syncthreads();

        const uint32_t sb = sb0 + (kt & 1) * STG * 2;
#pragma unroll
        for (int q = 0; q < 2; q++) {
            uint32_t ah[2][4], al[2][4], bh[NI][2], bl[NI][2];
            const uint32_t ka = sb + aoff + q * 32;
            LDSM4(ah[0][0], ah[0][1], ah[0][2], ah[0][3], ka);
            LDSM4(ah[1][0], ah[1][1], ah[1][2], ah[1][3], ka + 1280);
            LDSM4(al[0][0], al[0][1], al[0][2], al[0][3], ka + 5120);
            LDSM4(al[1][0], al[1][1], al[1][2], al[1][3], ka + 5120 + 1280);
            const uint32_t kb = sb + boff + q * 32;
#pragma unroll
            for (int p = 0; p < NI / 2; p++) {
                LDSM4(bh[2 * p][0], bh[2 * p][1], bh[2 * p + 1][0], bh[2 * p + 1][1],
                      kb + p * 1280);
                LDSM4(bl[2 * p][0], bl[2 * p][1], bl[2 * p + 1][0], bl[2 * p + 1][1],
                      kb + BN * 80 + p * 1280);
            }
#pragma unroll
            for (int mi = 0; mi < 2; mi++)
#pragma unroll
                for (int ni = 0; ni < NI; ni++) {
                    MMA_BF16(acc[mi][ni], ah[mi], bh[ni]);
                    MMA_BF16(acc[mi][ni], ah[mi], bl[ni]);
                    MMA_BF16(acc[mi][ni], al[mi], bh[ni]);
                }
        }
        __syncthreads();
    }

#pragma unroll
    for (int mi = 0; mi < 2; mi++) {
        const int row = bm + wm * 32 + mi * 16 + g;
#pragma unroll
        for (int ni = 0; ni < NI; ni++) {
            const int col = bn + wn * (BN / 4) + ni * 8 + 2 * ti;
            *(float2*)(C + (size_t)row * N + col) =
                make_float2(acc[mi][ni][0], acc[mi][ni][1]);
            *(float2*)(C + (size_t)(row + 8) * N + col) =
                make_float2(acc[mi][ni][2], acc[mi][ni][3]);
        }
    }
}

#define SMEM_B128 (2 * (5120 + 2 * 128 * 40) * 2)   // 61440
#define SMEM_B64  (2 * (5120 + 2 * 64 * 40) * 2)    // 40960

// ---------------------------------------------------------------------------
// FUSED per-step encoder kernel (256 threads), BK=128 phase 1, BK=64 phase 2.
// Phase 1 stage (bytes, stride-136-elem rows = 272 B, proven class):
//   A_hi@0 (17408)  A_lo@17408 (17408)  B_hi@34816 (34816)  B_lo@69632 (34816)
//   stage = 104448 B, 2 stages = 208896 B.
// Phase 2 (reuses smem): AC_hi@0 (17408 B), AC_lo@17408 B,
//   Wc stages @34816 B: per stage Wc_hi (18432 B, stride-72 rows) +
//   Wc_lo (+18432 B); stage = 36864 B, 2 stages.
// grid = (16 n-tiles, 8 batches) = 128 CTAs.
// ---------------------------------------------------------------------------
#define STG1B 104448
#define SMEM_STEP 208896

__global__ void __launch_bounds__(256) k_step()
{
    extern __shared__ __nv_bfloat16 smem[];
    const uint32_t sb0 = smem_u32(smem);

    const int tid = threadIdx.x;
    const int lane = tid & 31;
    const int wid = tid >> 5;
    const int wm = wid >> 2;
    const int wn = wid & 3;
    const int g = lane >> 2;
    const int ti = lane & 3;
    const int bm = blockIdx.x * 64;       // n-tile base
    const int b = blockIdx.y;             // batch

    const __nv_bfloat16* BH = g_hidTH + (size_t)b * 128 * 1024;
    const __nv_bfloat16* BL = g_hidTL + (size_t)b * 128 * 1024;

    const int i1 = (lane >> 3) & 1, i2 = lane >> 4, l7 = lane & 7;
    // phase-1 byte offsets (stride-136-elem rows; mi/p stride = 16*272 = 4352 B)
    const uint32_t aoff = ((wm * 32 + i1 * 8 + l7) * 136 + i2 * 8) * 2;
    const uint32_t boff = 34816 + ((wn * 32 + i2 * 8 + l7) * 136 + i1 * 8) * 2;
    // phase-2: AC stride-136 (unchanged), Wc stride-72 (p stride = 2304 B)
    const uint32_t aoff2 = aoff;          // same formula
    const uint32_t boff2 = ((wn * 32 + i2 * 8 + l7) * 72 + i1 * 8) * 2;

    float acc[2][4][4];
#pragma unroll
    for (int i = 0; i < 2; i++)
#pragma unroll
        for (int j = 0; j < 4; j++)
#pragma unroll
            for (int v = 0; v < 4; v++) acc[i][j][v] = 0.f;

    // ---------------- phase 1: AC = adj_tile @ hidT_b^T (BK=128) ---------------
    auto load_stage = [&](int stage, int k0) {
        const uint32_t sb = sb0 + stage * STG1B;
        // A: 64 rows x 128 k hi+lo (1024 chunks of 8 elems each)
#pragma unroll
        for (int rep = 0; rep < 4; rep++) {
            const int idx = tid + rep * 256;
            const int row = idx >> 4, ch = idx & 15;
            const uint32_t so = sb + (row * 136 + ch * 8) * 2;
            CPASYNC16(so, g_adjH + (size_t)(bm + row) * 1024 + k0 + ch * 8);
            CPASYNC16(so + 17408, g_adjL + (size_t)(bm + row) * 1024 + k0 + ch * 8);
        }
        // B: 128 rows x 128 k hi+lo (2048 chunks)
#pragma unroll
        for (int rep = 0; rep < 8; rep++) {
            const int idx = tid + rep * 256;
            const int row = idx >> 4, ch = idx & 15;
            const uint32_t so = sb + 34816 + (row * 136 + ch * 8) * 2;
            CPASYNC16(so, BH + (size_t)row * 1024 + k0 + ch * 8);
            CPASYNC16(so + 34816, BL + (size_t)row * 1024 + k0 + ch * 8);
        }
        CPCOMMIT();
    };

    load_stage(0, 0);

    for (int kt = 0; kt < 8; kt++) {
        if (kt + 1 < 8) { load_stage((kt + 1) & 1, (kt + 1) * 128); CPWAIT1(); }
        else            { CPWAIT0(); }
        __syncthreads();

        const uint32_t sb = sb0 + (kt & 1) * STG1B;
#pragma unroll
        for (int q = 0; q < 8; q++) {
            uint32_t ah[2][4], al[2][4], bh[4][2], bl[4][2];
            const uint32_t ka = sb + aoff + q * 32;
            LDSM4(ah[0][0], ah[0][1], ah[0][2], ah[0][3], ka);
            LDSM4(ah[1][0], ah[1][1], ah[1][2], ah[1][3], ka + 4352);
            LDSM4(al[0][0], al[0][1], al[0][2], al[0][3], ka + 17408);
            LDSM4(al[1][0], al[1][1], al[1][2], al[1][3], ka + 17408 + 4352);
            const uint32_t kb = sb + boff + q * 32;
#pragma unroll
            for (int p = 0; p < 2; p++) {
                LDSM4(bh[2 * p][0], bh[2 * p][1], bh[2 * p + 1][0], bh[2 * p + 1][1],
                      kb + p * 4352);
                LDSM4(bl[2 * p][0], bl[2 * p][1], bl[2 * p + 1][0], bl[2 * p + 1][1],
                      kb + 34816 + p * 4352);
            }
#pragma unroll
            for (int mi = 0; mi < 2; mi++)
#pragma unroll
                for (int ni = 0; ni < 4; ni++) {
                    MMA_BF16(acc[mi][ni], ah[mi], bh[ni]);
                    MMA_BF16(acc[mi][ni], ah[mi], bl[ni]);
                    MMA_BF16(acc[mi][ni], al[mi], bh[ni]);
                }
        }
        __syncthreads();
    }

    // ---- AC -> SMEM (split hi/lo), rows stride 136 (unchanged) ----
#pragma unroll
    for (int mi = 0; mi < 2; mi++) {
        const int row = wm * 32 + mi * 16 + g;
#pragma unroll
        for (int ni = 0; ni < 4; ni++) {
            const int col = wn * 32 + ni * 8 + 2 * ti;
            const uint32_t o0 = (uint32_t)(row * 136 + col) * 2;
            const uint32_t o1 = (uint32_t)((row + 8) * 136 + col) * 2;
            asm volatile("st.shared.b32 [%0], %1;" :: "r"(sb0 + o0),
                         "r"(pack2(acc[mi][ni][0], acc[mi][ni][1])));
            asm volatile("st.shared.b32 [%0], %1;" :: "r"(sb0 + 17408 + o0),
                         "r"(pack2lo(acc[mi][ni][0], acc[mi][ni][1])));
            asm volatile("st.shared.b32 [%0], %1;" :: "r"(sb0 + o1),
                         "r"(pack2(acc[mi][ni][2], acc[mi][ni][3])));
            asm volatile("st.shared.b32 [%0], %1;" :: "r"(sb0 + 17408 + o1),
                         "r"(pack2lo(acc[mi][ni][2], acc[mi][ni][3])));
        }
    }
    __syncthreads();

    // ---------------- phase 2: G = AC @ Wc^T (K=128, BK=64) ----------------
    auto loadWc = [&](int gi, int st) {
        const uint32_t base = sb0 + 34816 + st * 36864;
        const int nc2 = gi >> 1, kc64 = gi & 1;
        // 128 rows x 64 k hi+lo (1024 chunks)
#pragma unroll
        for (int rep = 0; rep < 4; rep++) {
            const int idx = tid + rep * 256;
            const int row = idx >> 3, ch = idx & 7;
            const uint32_t dst = base + (row * 72 + ch * 8) * 2;
            CPASYNC16(dst, g_wcH + (nc2 * 128 + row) * 128 + kc64 * 64 + ch * 8);
            CPASYNC16(dst + 18432, g_wcL + (nc2 * 128 + row) * 128 + kc64 * 64 + ch * 8);
        }
        CPCOMMIT();
    };

    loadWc(0, 0);

    for (int nc = 0; nc < 4; nc++) {
#pragma unroll
        for (int i = 0; i < 2; i++)
#pragma unroll
            for (int j = 0; j < 4; j++)
#pragma unroll
                for (int v = 0; v < 4; v++) acc[i][j][v] = 0.f;

        for (int kc64 = 0; kc64 < 2; kc64++) {
            const int gi = nc * 2 + kc64;
            if (gi < 7) { loadWc(gi + 1, (gi + 1) & 1); CPWAIT1(); }
            else        { CPWAIT0(); }
            __syncthreads();
            const uint32_t wcb = sb0 + 34816 + (gi & 1) * 36864;
#pragma unroll
            for (int q = 0; q < 4; q++) {
                uint32_t ah[2][4], al[2][4], bh[4][2], bl[4][2];
                const uint32_t ka = sb0 + aoff2 + (kc64 * 64 + q * 16) * 2;
                LDSM4(ah[0][0], ah[0][1], ah[0][2], ah[0][3], ka);
                LDSM4(ah[1][0], ah[1][1], ah[1][2], ah[1][3], ka + 4352);
                LDSM4(al[0][0], al[0][1], al[0][2], al[0][3], ka + 17408);
                LDSM4(al[1][0], al[1][1], al[1][2], al[1][3], ka + 17408 + 4352);
                const uint32_t kb = wcb + boff2 + q * 32;
#pragma unroll
                for (int p = 0; p < 2; p++) {
                    LDSM4(bh[2 * p][0], bh[2 * p][1], bh[2 * p + 1][0], bh[2 * p + 1][1],
                          kb + p * 2304);
                    LDSM4(bl[2 * p][0], bl[2 * p][1], bl[2 * p + 1][0], bl[2 * p + 1][1],
                          kb + 18432 + p * 2304);
                }
#pragma unroll
                for (int mi = 0; mi < 2; mi++)
#pragma unroll
                    for (int ni = 0; ni < 4; ni++) {
                        MMA_BF16(acc[mi][ni], ah[mi], bh[ni]);
                        MMA_BF16(acc[mi][ni], ah[mi], bl[ni]);
                        MMA_BF16(acc[mi][ni], al[mi], bh[ni]);
                    }
            }
            __syncthreads();
        }

        // write G chunk (node-major rows r = n*8+b)
#pragma unroll
        for (int mi = 0; mi < 2; mi++) {
            const int n0 = bm + wm * 32 + mi * 16 + g;
#pragma unroll
            for (int ni = 0; ni < 4; ni++) {
                const int col = nc * 128 + wn * 32 + ni * 8 + 2 * ti;
                *(float2*)(g_G + ((size_t)n0 * 8 + b) * 512 + col) =
                    make_float2(acc[mi][ni][0], acc[mi][ni][1]);
                *(float2*)(g_G + ((size_t)(n0 + 8) * 8 + b) * 512 + col) =
                    make_float2(acc[mi][ni][2], acc[mi][ni][3]);
            }
        }
    }
}

// ---------------------------------------------------------------------------
// Persistent fused decoder: 32 LSTM steps in ONE launch (proven).
// grid 128 CTAs x 512 threads. Writes the (b,n,h)-permuted output directly.
// ---------------------------------------------------------------------------
#define DEC_AH 0
#define DEC_AL 8704
#define DEC_B0 17408
#define DEC_STG 40960
#define DEC_ELEMS (DEC_B0 + 2 * DEC_STG)
#define DEC_SMEM (DEC_ELEMS * 2)

__global__ void __launch_bounds__(512) k_dec(const float* __restrict__ Gc,
                                             const float* __restrict__ bih,
                                             const float* __restrict__ bhh,
                                             float* __restrict__ out)
{
    extern __shared__ __nv_bfloat16 sm[];
    __shared__ float sbias[512];
    const uint32_t sb = smem_u32(sm);

    const int tid = threadIdx.x;
    const int lane = tid & 31;
    const int wid = tid >> 5;
    const int wm = wid >> 3;
    const int wn = wid & 7;
    const int g = lane >> 2;
    const int ti = lane & 3;
    const int bm = blockIdx.x * 64;

    if (tid < 512) sbias[tid] = bih[tid] + bhh[tid];
    for (int i = tid; i < 8704; i += 512) { sm[DEC_AH + i] = __float2bfloat16(0.f);
                                            sm[DEC_AL + i] = __float2bfloat16(0.f); }

    float cxr[16];
#pragma unroll
    for (int i = 0; i < 16; i++) cxr[i] = 0.f;

    float acc[2][8][4];
#pragma unroll
    for (int mi = 0; mi < 2; mi++)
#pragma unroll
        for (int j = 0; j < 8; j++)
#pragma unroll
            for (int v = 0; v < 4; v++) acc[mi][j][v] = 0.f;

    auto loadB = [&](int kc, int st) {
        const uint32_t base = sb + (DEC_B0 + st * DEC_STG) * 2;
#pragma unroll
        for (int rep = 0; rep < 4; rep++) {
            const int idx = tid + rep * 512;
            const int row = idx >> 2;
            const int qq = idx & 3;
            const uint32_t dst = base + (row * 40 + qq * 8) * 2;
            CPASYNC16(dst, g_whhH + row * 128 + kc * 32 + qq * 8);
            CPASYNC16(dst + 20480 * 2, g_whhL + row * 128 + kc * 32 + qq * 8);
        }
        CPCOMMIT();
    };

    const int i1 = (lane >> 3) & 1, i2 = lane >> 4, l7 = lane & 7;
    const uint32_t aoff = ((wm * 32 + i1 * 8 + l7) * 136 + i2 * 8) * 2;
    const uint32_t boffrel = ((wn * 16 + i2 * 8 + l7) * 40 + i1 * 8) * 2;

    loadB(0, 0);

    for (int step = 0; step < Ss; step++) {
        for (int kc = 0; kc < 4; kc++) {
            const int gi = step * 4 + kc;
            loadB((gi + 1) & 3, (gi + 1) & 1);
            CPWAIT1();
            __syncthreads();
            const uint32_t bbase = sb + (DEC_B0 + (gi & 1) * DEC_STG) * 2;
#pragma unroll
            for (int q = 0; q < 2; q++) {
                uint32_t ah[2][4], al[2][4];
                const uint32_t ka = sb + aoff + (kc * 32 + q * 16) * 2;
                LDSM4(ah[0][0], ah[0][1], ah[0][2], ah[0][3], ka);
                LDSM4(ah[1][0], ah[1][1], ah[1][2], ah[1][3], ka + 4352);
                LDSM4(al[0][0], al[0][1], al[0][2], al[0][3], ka + 17408);
                LDSM4(al[1][0], al[1][1], al[1][2], al[1][3], ka + 17408 + 4352);
#pragma unroll
                for (int pp = 0; pp < 4; pp++) {
                    uint32_t bh[2][2], bl[2][2];
                    const uint32_t kb = bbase + boffrel + q * 32 + pp * 10240;
                    LDSM4(bh[0][0], bh[0][1], bh[1][0], bh[1][1], kb);
                    LDSM4(bl[0][0], bl[0][1], bl[1][0], bl[1][1], kb + 40960);
#pragma unroll
                    for (int mi = 0; mi < 2; mi++)
#pragma unroll
                        for (int jj = 0; jj < 2; jj++) {
                            float* a = acc[mi][pp * 2 + jj];
                            MMA_BF16(a, ah[mi], bh[jj]);
                            MMA_BF16(a, ah[mi], bl[jj]);
                            MMA_BF16(a, al[mi], bh[jj]);
                        }
                }
            }
            __syncthreads();
        }
        const int last = (step == Ss - 1);
#pragma unroll
        for (int mi = 0; mi < 2; mi++)
#pragma unroll
            for (int rh = 0; rh < 2; rh++)
#pragma unroll
                for (int sub = 0; sub < 2; sub++)
#pragma unroll
                    for (int p = 0; p < 2; p++) {
                        const int rowLoc = wm * 32 + mi * 16 + rh * 8 + g;
                        const int h = wn * 16 + sub * 8 + 2 * ti + p;
                        const int grow = bm + rowLoc;
                        const int ci = mi * 8 + rh * 4 + sub * 2 + p;
                        float ig = acc[mi][0 + sub][rh * 2 + p] + Gc[(size_t)grow * 512 + h] + sbias[h];
                        float fg = acc[mi][2 + sub][rh * 2 + p] + Gc[(size_t)grow * 512 + 128 + h] + sbias[128 + h];
                        float gt = acc[mi][4 + sub][rh * 2 + p] + Gc[(size_t)grow * 512 + 256 + h] + sbias[256 + h];
                        float og = acc[mi][6 + sub][rh * 2 + p] + Gc[(size_t)grow * 512 + 384 + h] + sbias[384 + h];
                        ig = fsigm(ig); fg = fsigm(fg); gt = ftanh(gt); og = fsigm(og);
                        const float cx = fg * cxr[ci] + ig * gt;
                        cxr[ci] = cx;
                        const float hxv = og * ftanh(cx);
                        __nv_bfloat16 hh, ll;
                        splitHL(hxv, hh, ll);
                        sm[DEC_AH + rowLoc * 136 + h] = hh;
                        sm[DEC_AL + rowLoc * 136 + h] = ll;
                        if (last) {
                            const int bq = grow & 7, n = grow >> 3;
                            out[((size_t)bq * 1024 + n) * 128 + h] = hxv;
                        }
                        acc[mi][0 + sub][rh * 2 + p] = 0.f;
                        acc[mi][2 + sub][rh * 2 + p] = 0.f;
                        acc[mi][4 + sub][rh * 2 + p] = 0.f;
                        acc[mi][6 + sub][rh * 2 + p] = 0.f;
                    }
        __syncthreads();
    }
}

// ---------------------------------------------------------------------------
// Converters & small kernels
// ---------------------------------------------------------------------------
__global__ void c_splitHL(const float* __restrict__ src,
                          __nv_bfloat16* __restrict__ dH, __nv_bfloat16* __restrict__ dL,
                          int Kc, int Kp)
{
    const int row = blockIdx.y;
    const int k = blockIdx.x * 256 + threadIdx.x;
    if (k >= Kp) return;
    const float v = (k < Kc) ? src[(size_t)row * Kc + k] : 0.f;
    __nv_bfloat16 h, l;
    splitHL(v, h, l);
    dH[(size_t)row * Kp + k] = h;
    dL[(size_t)row * Kp + k] = l;
}

__global__ void c_split_x(const float* __restrict__ x)
{
    const int j = blockIdx.y;
    const int k = blockIdx.x * 256 + threadIdx.x;
    const int s = j >> 5, b = (j >> 2) & 7, f = j & 3;
    const float v = x[((size_t)(b * Ss + s) * Nn + k) * 4 + f];
    __nv_bfloat16 h, l;
    splitHL(v, h, l);
    g_xTH[(size_t)j * 1024 + k] = h;
    g_xTL[(size_t)j * 1024 + k] = l;
}

__global__ void c_wprep(const float* __restrict__ W1, const float* __restrict__ W2)
{
    const int idx = blockIdx.x * 256 + threadIdx.x;
    if (idx < 512 * 128) {
        const int gate = idx >> 7, k = idx & 127;
        const int c = k + 4;
        const float v = (gate < G3) ? W1[c * G3 + gate] : W2[c * Hh + (gate - G3)];
        __nv_bfloat16 h, l;
        splitHL(v, h, l);
        g_wcH[idx] = h;
        g_wcL[idx] = l;
    }
    if (idx < 4 * 512) {
        const int k = idx >> 9, c = idx & 511;
        g_W4[idx] = (c < G3) ? W1[k * G3 + c] : W2[k * Hh + (c - G3)];
    }
}

__global__ void k_zero()
{
    const int idx = blockIdx.x * blockDim.x + threadIdx.x;   // 1M threads
    *(float4*)(g_G + (size_t)idx * 4) = make_float4(0.f, 0.f, 0.f, 0.f);
    g_csum[idx] = 0.f;
}

// Encoder elementwise: flat-chunk gate indexing + AX rank-4 correction,
// fused transposed hi/lo split; on last step also writes split csum.
__global__ void k_enc_elem(const float* __restrict__ b1, const float* __restrict__ b2,
                           int s, int last)
{
    __shared__ float t[32][33];
    const int b = blockIdx.x >> 7;
    const int nt = (blockIdx.x >> 2) & 31;
    const int ht = blockIdx.x & 3;
    const int n0 = nt * 32, h0 = ht * 32;
    const int hl = threadIdx.x & 31;
    const int w8 = threadIdx.x >> 5;

#pragma unroll
    for (int q = 0; q < 4; q++) {
        const int nl = w8 + q * 8;
        const int n = n0 + nl;
        const int h = h0 + hl;
        const int j = n * 128 + h;
        const int ji = j + NHf;
        const int ni = ji / G3, ci = ji - ni * G3;
        const int jo = j + 2 * NHf;
        const int no = jo / G3, co = jo - no * G3;
        const int sb4 = s * 32 + b * 4;

        float igp = g_G[(size_t)(ni * 8 + b) * 512 + ci] + b1[ci];
        float ogp = g_G[(size_t)(no * 8 + b) * 512 + co] + b1[co];
        float csp = g_G[(size_t)(n * 8 + b) * 512 + G3 + h] + b2[h];
#pragma unroll
        for (int k = 0; k < 4; k++) {
            igp += g_AX[(size_t)ni * 1024 + sb4 + k] * g_W4[k * 512 + ci];
            ogp += g_AX[(size_t)no * 1024 + sb4 + k] * g_W4[k * 512 + co];
            csp += g_AX[(size_t)n * 1024 + sb4 + k] * g_W4[k * 512 + G3 + h];
        }
        const float hn = fsigm(ogp) * ftanh(fsigm(igp) * ftanh(csp));
        const size_t co2 = (size_t)(n * 8 + b) * 128 + h;
        const float cs2 = g_csum[co2] + hn;
        g_csum[co2] = cs2;
        if (last) {
            __nv_bfloat16 ch, cl;
            splitHL(cs2, ch, cl);
            g_csH[co2] = ch;
            g_csL[co2] = cl;
        }
        t[hl][nl] = hn;
    }
    __syncthreads();
#pragma unroll
    for (int q = 0; q < 4; q++) {
        const int h2 = w8 + q * 8;
        const float v = t[h2][hl];
        __nv_bfloat16 hh, ll;
        splitHL(v, hh, ll);
        g_hidTH[(size_t)(b * 128 + h0 + h2) * 1024 + n0 + hl] = hh;
        g_hidTL[(size_t)(b * 128 + h0 + h2) * 1024 + n0 + hl] = ll;
    }
}

// ---------------------------------------------------------------------------
// Launch (single stream)
// ---------------------------------------------------------------------------
extern "C" void kernel_launch(void* const* d_in, const int* in_sizes, int n_in,
                              void* d_out, int out_size)
{
    (void)in_sizes; (void)n_in; (void)out_size;
    const float* x   = (const float*)d_in[0];
    const float* adj = (const float*)d_in[1];
    const float* W1  = (const float*)d_in[2];
    const float* b1  = (const float*)d_in[3];
    const float* W2  = (const float*)d_in[4];
    const float* b2  = (const float*)d_in[5];
    const float* Wih = (const float*)d_in[6];
    const float* Whh = (const float*)d_in[7];
    const float* bih = (const float*)d_in[8];
    const float* bhh = (const float*)d_in[9];
    float* out = (float*)d_out;

    cudaFuncSetAttribute(gemmA<128>, cudaFuncAttributeMaxDynamicSharedMemorySize, SMEM_B128);
    cudaFuncSetAttribute(gemmA<64>, cudaFuncAttributeMaxDynamicSharedMemorySize, SMEM_B64);
    cudaFuncSetAttribute(k_step, cudaFuncAttributeMaxDynamicSharedMemorySize, SMEM_STEP);
    cudaFuncSetAttribute(k_dec, cudaFuncAttributeMaxDynamicSharedMemorySize, DEC_SMEM);

    __nv_bfloat16 *pAdjH, *pAdjL, *pXH, *pXL, *pWiH, *pWiL, *pWhH, *pWhL, *pCsH, *pCsL;
    float *pAX, *pGc;
    cudaGetSymbolAddress((void**)&pAdjH, g_adjH);
    cudaGetSymbolAddress((void**)&pAdjL, g_adjL);
    cudaGetSymbolAddress((void**)&pXH, g_xTH);
    cudaGetSymbolAddress((void**)&pXL, g_xTL);
    cudaGetSymbolAddress((void**)&pWiH, g_wihH);
    cudaGetSymbolAddress((void**)&pWiL, g_wihL);
    cudaGetSymbolAddress((void**)&pWhH, g_whhH);
    cudaGetSymbolAddress((void**)&pWhL, g_whhL);
    cudaGetSymbolAddress((void**)&pCsH, g_csH);
    cudaGetSymbolAddress((void**)&pCsL, g_csL);
    cudaGetSymbolAddress((void**)&pAX, g_AX);
    cudaGetSymbolAddress((void**)&pGc, g_Gc);

    k_zero<<<4096, 256>>>();
    c_wprep<<<256, 256>>>(W1, W2);
    c_splitHL<<<dim3(4, 1024), 256>>>(adj, pAdjH, pAdjL, 1024, 1024);
    c_split_x<<<dim3(4, 1024), 256>>>(x);
    c_splitHL<<<dim3(1, 512), 256>>>(Wih, pWiH, pWiL, 128, 128);
    c_splitHL<<<dim3(1, 512), 256>>>(Whh, pWhH, pWhL, 128, 128);

    // AX = adj @ x^T (all steps)
    gemmA<64><<<dim3(16, 16), 256, SMEM_B64>>>(pAdjH, pAdjL, pXH, pXL, pAX, 1024, 1024);

    // ---------------- Encoder: 32 recurrent steps (2 kernels each) --------
    for (int s = 0; s < Ss; s++) {
        if (s) k_step<<<dim3(16, 8), 256, SMEM_STEP>>>();
        k_enc_elem<<<1024, 256>>>(b1, b2, s, s == Ss - 1);
    }

    // ---------------- Decoder ----------------
    gemmA<128><<<dim3(4, 128), 256, SMEM_B128>>>(pCsH, pCsL, pWiH, pWiL, pGc, 128, 512);
    k_dec<<<128, 512, DEC_SMEM>>>(pGc, bih, bhh, out);
}